// round 3
// baseline (speedup 1.0000x reference)
#include <cuda_runtime.h>

#define Bn 8
#define Tn 4096
#define Cn 128
#define HSn 64
#define BQ 128
#define BK 64

// scale = 1/sqrt(C) folded with log2(e) so we can use ex2.approx
#define QSCALE (0.08838834764831845f * 1.4426950408889634f)

// Scratch (device globals — no allocation allowed in kernel_launch)
__device__ float g_Q[Bn * Tn * HSn];
__device__ float g_K[Bn * Tn * HSn];
__device__ float g_V[Bn * Tn * HSn];
__device__ int   g_len[Bn];

__device__ __forceinline__ float exp2_approx(float x) {
    float y;
    asm("ex2.approx.ftz.f32 %0, %1;" : "=f"(y) : "f"(x));
    return y;
}

// ---------------------------------------------------------------------------
// Kernel 0: per-batch valid length (mask is a prefix mask; length = sum)
// ---------------------------------------------------------------------------
__global__ void len_kernel(const int* __restrict__ mask) {
    int b = blockIdx.x;
    int tid = threadIdx.x;
    int sum = 0;
    for (int i = tid; i < Tn; i += 256) sum += mask[b * Tn + i];
    __shared__ int red[8];
    #pragma unroll
    for (int off = 16; off > 0; off >>= 1)
        sum += __shfl_down_sync(0xffffffffu, sum, off);
    if ((tid & 31) == 0) red[tid >> 5] = sum;
    __syncthreads();
    if (tid == 0) {
        int s = 0;
        #pragma unroll
        for (int w = 0; w < 8; w++) s += red[w];
        g_len[b] = s;
    }
}

// ---------------------------------------------------------------------------
// Kernel 1: fused QKV projection + RoPE.
// 8 rows per block, 16 threads per row, each thread computes 4 contiguous
// head dims (two full RoPE pairs -> rotation entirely in registers).
// ---------------------------------------------------------------------------
__global__ __launch_bounds__(128) void qkv_kernel(
    const float* __restrict__ x,
    const float* __restrict__ Wq,
    const float* __restrict__ Wk,
    const float* __restrict__ Wv,
    const float* __restrict__ fcos,
    const float* __restrict__ fsin)
{
    __shared__ float xs[8 * Cn];
    int tid = threadIdx.x;
    int r   = tid >> 4;          // 0..7: row within block
    int d0  = (tid & 15) << 2;   // 0,4,...,60

    long gr0 = (long)blockIdx.x * 8;
    // cooperative load of 8 contiguous x rows (1024 floats)
    const float4* xg = (const float4*)(x + gr0 * Cn);
    float4* xs4 = (float4*)xs;
    xs4[tid]       = xg[tid];
    xs4[tid + 128] = xg[tid + 128];
    __syncthreads();

    long gr = gr0 + r;
    int t = (int)(gr % Tn);

    float q[4] = {0.f, 0.f, 0.f, 0.f};
    float k[4] = {0.f, 0.f, 0.f, 0.f};
    float v[4] = {0.f, 0.f, 0.f, 0.f};
    const float* xr = xs + r * Cn;

    #pragma unroll 4
    for (int c = 0; c < Cn; c++) {
        float xv = xr[c];
        float4 wq = *(const float4*)(Wq + c * HSn + d0);
        float4 wk = *(const float4*)(Wk + c * HSn + d0);
        float4 wv = *(const float4*)(Wv + c * HSn + d0);
        q[0] += xv * wq.x; q[1] += xv * wq.y; q[2] += xv * wq.z; q[3] += xv * wq.w;
        k[0] += xv * wk.x; k[1] += xv * wk.y; k[2] += xv * wk.z; k[3] += xv * wk.w;
        v[0] += xv * wv.x; v[1] += xv * wv.y; v[2] += xv * wv.z; v[3] += xv * wv.w;
    }

    // fold softmax scale (and log2e) into q before rotation (commutes)
    q[0] *= QSCALE; q[1] *= QSCALE; q[2] *= QSCALE; q[3] *= QSCALE;

    // RoPE: pairs (d0,d0+1) and (d0+2,d0+3)
    int p0 = d0 >> 1;
    float c0 = fcos[t * (HSn / 2) + p0];
    float s0 = fsin[t * (HSn / 2) + p0];
    float c1 = fcos[t * (HSn / 2) + p0 + 1];
    float s1 = fsin[t * (HSn / 2) + p0 + 1];

    float4 qo, ko, vo;
    qo.x = q[0] * c0 - q[1] * s0;  qo.y = q[0] * s0 + q[1] * c0;
    qo.z = q[2] * c1 - q[3] * s1;  qo.w = q[2] * s1 + q[3] * c1;
    ko.x = k[0] * c0 - k[1] * s0;  ko.y = k[0] * s0 + k[1] * c0;
    ko.z = k[2] * c1 - k[3] * s1;  ko.w = k[2] * s1 + k[3] * c1;
    vo.x = v[0]; vo.y = v[1]; vo.z = v[2]; vo.w = v[3];

    long base = gr * HSn + d0;
    *(float4*)(g_Q + base) = qo;
    *(float4*)(g_K + base) = ko;
    *(float4*)(g_V + base) = vo;
}

// ---------------------------------------------------------------------------
// Kernel 2: flash attention. 1 query per thread (128 queries/CTA),
// q/o accumulators in registers, K/V streamed through shared in 64-key tiles,
// online softmax in 16-key chunks (amortized rescale).
// ---------------------------------------------------------------------------
__global__ __launch_bounds__(128, 2) void flash_kernel(float* __restrict__ out)
{
    __shared__ float Ks[BK * HSn];
    __shared__ float Vs[BK * HSn];

    int b   = blockIdx.y;
    int q0  = blockIdx.x * BQ;
    int tid = threadIdx.x;
    int qi  = q0 + tid;

    long qbase = ((long)b * Tn + qi) * HSn;

    float q[HSn], o[HSn];
    #pragma unroll
    for (int d = 0; d < HSn; d += 4) {
        float4 t4 = *(const float4*)(g_Q + qbase + d);
        q[d] = t4.x; q[d + 1] = t4.y; q[d + 2] = t4.z; q[d + 3] = t4.w;
        o[d] = 0.f;  o[d + 1] = 0.f;  o[d + 2] = 0.f;  o[d + 3] = 0.f;
    }

    float m = -1e30f, l = 0.f;
    int len  = g_len[b];
    int kend = min(q0 + BQ, len);   // keys must satisfy k <= qi AND k < len

    for (int kt = 0; kt < kend; kt += BK) {
        __syncthreads();
        {
            const float4* kg = (const float4*)(g_K + ((long)b * Tn + kt) * HSn);
            const float4* vg = (const float4*)(g_V + ((long)b * Tn + kt) * HSn);
            float4* ks4 = (float4*)Ks;
            float4* vs4 = (float4*)Vs;
            #pragma unroll
            for (int i = 0; i < 8; i++) {
                ks4[tid + i * 128] = kg[tid + i * 128];
                vs4[tid + i * 128] = vg[tid + i * 128];
            }
        }
        __syncthreads();

        #pragma unroll 1
        for (int j0 = 0; j0 < BK; j0 += 16) {
            float s[16];
            #pragma unroll
            for (int jj = 0; jj < 16; jj++) {
                const float* kr = Ks + (j0 + jj) * HSn;
                float acc = 0.f;
                #pragma unroll
                for (int d = 0; d < HSn; d += 4) {
                    float4 kv = *(const float4*)(kr + d);
                    acc += q[d]     * kv.x;
                    acc += q[d + 1] * kv.y;
                    acc += q[d + 2] * kv.z;
                    acc += q[d + 3] * kv.w;
                }
                int kk = kt + j0 + jj;
                s[jj] = (kk <= qi && kk < len) ? acc : -2e30f;
            }

            float mx = s[0];
            #pragma unroll
            for (int jj = 1; jj < 16; jj++) mx = fmaxf(mx, s[jj]);
            float mnew  = fmaxf(m, mx);
            float alpha = exp2_approx(m - mnew);   // 0 on first pass (ftz)
            l *= alpha;
            #pragma unroll
            for (int d = 0; d < HSn; d++) o[d] *= alpha;

            #pragma unroll
            for (int jj = 0; jj < 16; jj++) {
                float p = exp2_approx(s[jj] - mnew);
                l += p;
                const float* vr = Vs + (j0 + jj) * HSn;
                #pragma unroll
                for (int d = 0; d < HSn; d += 4) {
                    float4 vv = *(const float4*)(vr + d);
                    o[d]     += p * vv.x;
                    o[d + 1] += p * vv.y;
                    o[d + 2] += p * vv.z;
                    o[d + 3] += p * vv.w;
                }
            }
            m = mnew;
        }
    }

    float inv = 1.0f / l;   // l >= 1 (max key contributes exp2(0)=1)
    #pragma unroll
    for (int d = 0; d < HSn; d += 4) {
        float4 r4;
        r4.x = o[d] * inv; r4.y = o[d + 1] * inv;
        r4.z = o[d + 2] * inv; r4.w = o[d + 3] * inv;
        *(float4*)(out + qbase + d) = r4;
    }
}

// ---------------------------------------------------------------------------
extern "C" void kernel_launch(void* const* d_in, const int* in_sizes, int n_in,
                              void* d_out, int out_size) {
    const float* x    = (const float*)d_in[0];
    const float* Wq   = (const float*)d_in[1];
    const float* Wk   = (const float*)d_in[2];
    const float* Wv   = (const float*)d_in[3];
    const float* fcos = (const float*)d_in[4];
    const float* fsin = (const float*)d_in[5];
    const int*   mask = (const int*)d_in[6];
    float* out = (float*)d_out;

    len_kernel<<<Bn, 256>>>(mask);
    qkv_kernel<<<Bn * Tn / 8, 128>>>(x, Wq, Wk, Wv, fcos, fsin);
    dim3 grid(Tn / BQ, Bn);
    flash_kernel<<<grid, 128>>>(out);
}

// round 5
// speedup vs baseline: 6.5331x; 6.5331x over previous
#include <cuda_runtime.h>
#include <cuda_fp16.h>
#include <cstdint>
#include <stdint.h>

#define Bn 8
#define Tn 4096
#define Cn 128
#define HSn 64

// scale = 1/sqrt(C) folded with log2(e) so we can use ex2.approx
#define QSCALE (0.08838834764831845f * 1.4426950408889634f)

// Scratch (device globals — no allocation allowed in kernel_launch)
__device__ __align__(16) __half g_Q[Bn * Tn * HSn];
__device__ __align__(16) __half g_K[Bn * Tn * HSn];
__device__ __align__(16) __half g_V[Bn * Tn * HSn];
__device__ int g_len[Bn];

__device__ __forceinline__ float exp2_approx(float x) {
    float y;
    asm("ex2.approx.ftz.f32 %0, %1;" : "=f"(y) : "f"(x));
    return y;
}

__device__ __forceinline__ unsigned smem_u32(const void* p) {
    return (unsigned)__cvta_generic_to_shared(p);
}

__device__ __forceinline__ void mma16816(float* c, const unsigned* a,
                                         unsigned b0, unsigned b1) {
    asm volatile(
        "mma.sync.aligned.m16n8k16.row.col.f32.f16.f16.f32 "
        "{%0,%1,%2,%3}, {%4,%5,%6,%7}, {%8,%9}, {%0,%1,%2,%3};\n"
        : "+f"(c[0]), "+f"(c[1]), "+f"(c[2]), "+f"(c[3])
        : "r"(a[0]), "r"(a[1]), "r"(a[2]), "r"(a[3]), "r"(b0), "r"(b1));
}

__device__ __forceinline__ void ldsm4(unsigned* r, unsigned addr) {
    asm volatile("ldmatrix.sync.aligned.m8n8.x4.shared.b16 {%0,%1,%2,%3}, [%4];"
                 : "=r"(r[0]), "=r"(r[1]), "=r"(r[2]), "=r"(r[3]) : "r"(addr));
}

__device__ __forceinline__ void ldsm4t(unsigned* r, unsigned addr) {
    asm volatile("ldmatrix.sync.aligned.m8n8.x4.trans.shared.b16 {%0,%1,%2,%3}, [%4];"
                 : "=r"(r[0]), "=r"(r[1]), "=r"(r[2]), "=r"(r[3]) : "r"(addr));
}

// ---------------------------------------------------------------------------
// Kernel 0: per-batch valid length (mask is a prefix mask; length = sum)
// ---------------------------------------------------------------------------
__global__ void len_kernel(const int* __restrict__ mask) {
    int b = blockIdx.x;
    int tid = threadIdx.x;
    int sum = 0;
    for (int i = tid; i < Tn; i += 256) sum += mask[b * Tn + i];
    __shared__ int red[8];
    #pragma unroll
    for (int off = 16; off > 0; off >>= 1)
        sum += __shfl_down_sync(0xffffffffu, sum, off);
    if ((tid & 31) == 0) red[tid >> 5] = sum;
    __syncthreads();
    if (tid == 0) {
        int s = 0;
        #pragma unroll
        for (int w = 0; w < 8; w++) s += red[w];
        g_len[b] = s;
    }
}

// ---------------------------------------------------------------------------
// Kernel 1: fused QKV projection + RoPE, fp16 output (Q pre-scaled).
// ---------------------------------------------------------------------------
__global__ __launch_bounds__(128) void qkv_kernel(
    const float* __restrict__ x,
    const float* __restrict__ Wq,
    const float* __restrict__ Wk,
    const float* __restrict__ Wv,
    const float* __restrict__ fcos,
    const float* __restrict__ fsin)
{
    __shared__ float xs[8 * Cn];
    int tid = threadIdx.x;
    int r   = tid >> 4;          // 0..7: row within block
    int d0  = (tid & 15) << 2;   // 0,4,...,60

    long gr0 = (long)blockIdx.x * 8;
    const float4* xg = (const float4*)(x + gr0 * Cn);
    float4* xs4 = (float4*)xs;
    xs4[tid]       = xg[tid];
    xs4[tid + 128] = xg[tid + 128];
    __syncthreads();

    long gr = gr0 + r;
    int t = (int)(gr % Tn);

    float q[4] = {0.f, 0.f, 0.f, 0.f};
    float k[4] = {0.f, 0.f, 0.f, 0.f};
    float v[4] = {0.f, 0.f, 0.f, 0.f};
    const float* xr = xs + r * Cn;

    #pragma unroll 4
    for (int c = 0; c < Cn; c++) {
        float xv = xr[c];
        float4 wq = *(const float4*)(Wq + c * HSn + d0);
        float4 wk = *(const float4*)(Wk + c * HSn + d0);
        float4 wv = *(const float4*)(Wv + c * HSn + d0);
        q[0] += xv * wq.x; q[1] += xv * wq.y; q[2] += xv * wq.z; q[3] += xv * wq.w;
        k[0] += xv * wk.x; k[1] += xv * wk.y; k[2] += xv * wk.z; k[3] += xv * wk.w;
        v[0] += xv * wv.x; v[1] += xv * wv.y; v[2] += xv * wv.z; v[3] += xv * wv.w;
    }

    q[0] *= QSCALE; q[1] *= QSCALE; q[2] *= QSCALE; q[3] *= QSCALE;

    int p0 = d0 >> 1;
    float c0 = fcos[t * (HSn / 2) + p0];
    float s0 = fsin[t * (HSn / 2) + p0];
    float c1 = fcos[t * (HSn / 2) + p0 + 1];
    float s1 = fsin[t * (HSn / 2) + p0 + 1];

    union { __half2 h[2]; uint2 u; } pq, pk, pv;
    pq.h[0] = __floats2half2_rn(q[0] * c0 - q[1] * s0, q[0] * s0 + q[1] * c0);
    pq.h[1] = __floats2half2_rn(q[2] * c1 - q[3] * s1, q[2] * s1 + q[3] * c1);
    pk.h[0] = __floats2half2_rn(k[0] * c0 - k[1] * s0, k[0] * s0 + k[1] * c0);
    pk.h[1] = __floats2half2_rn(k[2] * c1 - k[3] * s1, k[2] * s1 + k[3] * c1);
    pv.h[0] = __floats2half2_rn(v[0], v[1]);
    pv.h[1] = __floats2half2_rn(v[2], v[3]);

    long base = gr * HSn + d0;
    *(uint2*)(g_Q + base) = pq.u;
    *(uint2*)(g_K + base) = pk.u;
    *(uint2*)(g_V + base) = pv.u;
}

// ---------------------------------------------------------------------------
// Kernel 2: flash attention with HMMA (mma.sync m16n8k16 fp16->fp32).
// 4 warps/CTA, 16 queries per warp (BQ=64). K/V in 64x64 fp16 smem tiles,
// XOR-swizzled for conflict-free ldmatrix. S fragments reused as P A-frags.
// ---------------------------------------------------------------------------
__global__ __launch_bounds__(128) void flash_kernel(float* __restrict__ out)
{
    __shared__ __half Ks[64 * HSn];
    __shared__ __half Vs[64 * HSn];

    int b = blockIdx.y;
    int q0 = blockIdx.x * 64;
    int tid = threadIdx.x, warp = tid >> 5, lane = tid & 31;
    int g = lane >> 2, t = lane & 3;
    int qw = q0 + warp * 16;
    int len = g_len[b];
    int kend = min(q0 + 64, len);

    // Q fragments: 4 k-steps x 4 regs (a0a1 row g | a2a3 row g+8 | +8 cols)
    unsigned qf[4][4];
    {
        const __half* Qb = g_Q + ((long)b * Tn + qw) * HSn;
        #pragma unroll
        for (int ks = 0; ks < 4; ks++) {
            qf[ks][0] = *(const unsigned*)(Qb + (g    ) * HSn + ks * 16 + 2 * t);
            qf[ks][1] = *(const unsigned*)(Qb + (g + 8) * HSn + ks * 16 + 2 * t);
            qf[ks][2] = *(const unsigned*)(Qb + (g    ) * HSn + ks * 16 + 2 * t + 8);
            qf[ks][3] = *(const unsigned*)(Qb + (g + 8) * HSn + ks * 16 + 2 * t + 8);
        }
    }

    float o[8][4];
    #pragma unroll
    for (int n = 0; n < 8; n++) { o[n][0] = o[n][1] = o[n][2] = o[n][3] = 0.f; }
    float m0 = -1e30f, m1 = -1e30f, l0 = 0.f, l1 = 0.f;

    // ldmatrix lane address precompute (byte addresses; swizzle: chunk ^= row&7)
    unsigned ksb = smem_u32(Ks), vsb = smem_u32(Vs);
    int grp = lane >> 3, r8 = lane & 7;
    unsigned kAdr[4], kSw[4], vAdr[4], vSw[4];
    #pragma unroll
    for (int p = 0; p < 4; p++)
        kAdr[p] = ksb + (unsigned)(16 * p + 8 * (grp >> 1) + r8) * 128u;
    #pragma unroll
    for (int ks = 0; ks < 4; ks++)
        kSw[ks] = (unsigned)(((2 * ks + (grp & 1)) ^ r8) * 16);
    #pragma unroll
    for (int kv = 0; kv < 4; kv++)
        vAdr[kv] = vsb + (unsigned)(16 * kv + 8 * (grp & 1) + r8) * 128u;
    #pragma unroll
    for (int pv = 0; pv < 4; pv++)
        vSw[pv] = (unsigned)(((2 * pv + (grp >> 1)) ^ r8) * 16);

    const __half* Kg = g_K + (long)b * Tn * HSn;
    const __half* Vg = g_V + (long)b * Tn * HSn;

    for (int kt = 0; kt < kend; kt += 64) {
        __syncthreads();
        #pragma unroll
        for (int i = 0; i < 4; i++) {
            int cid = tid + i * 128;               // 0..511 16B-chunks
            int row = cid >> 3, c = cid & 7;
            uint4 k4 = *(const uint4*)(Kg + (long)(kt + row) * HSn + c * 8);
            uint4 v4 = *(const uint4*)(Vg + (long)(kt + row) * HSn + c * 8);
            int dst = row * HSn + ((c ^ (row & 7)) * 8);
            *(uint4*)(Ks + dst) = k4;
            *(uint4*)(Vs + dst) = v4;
        }
        __syncthreads();

        // S = Q K^T  (8 n-tiles of 8 keys, 4 k-steps of 16 dims)
        float s[8][4];
        #pragma unroll
        for (int n = 0; n < 8; n++) { s[n][0] = s[n][1] = s[n][2] = s[n][3] = 0.f; }
        #pragma unroll
        for (int ks = 0; ks < 4; ks++) {
            #pragma unroll
            for (int p = 0; p < 4; p++) {
                unsigned kb[4];
                ldsm4(kb, kAdr[p] + kSw[ks]);
                mma16816(s[2 * p],     qf[ks], kb[0], kb[1]);
                mma16816(s[2 * p + 1], qf[ks], kb[2], kb[3]);
            }
        }

        // mask (only diagonal / tail tiles)
        bool full = (kt + 63 <= qw) && (kt + 64 <= len);
        if (!full) {
            int rg = qw + g, rg8 = rg + 8;
            #pragma unroll
            for (int n = 0; n < 8; n++) {
                int k0 = kt + n * 8 + 2 * t;
                if (!(k0     <= rg  && k0     < len)) s[n][0] = -1e30f;
                if (!(k0 + 1 <= rg  && k0 + 1 < len)) s[n][1] = -1e30f;
                if (!(k0     <= rg8 && k0     < len)) s[n][2] = -1e30f;
                if (!(k0 + 1 <= rg8 && k0 + 1 < len)) s[n][3] = -1e30f;
            }
        }

        // online softmax (rows g and g+8)
        float mr0 = s[0][0], mr1 = s[0][2];
        #pragma unroll
        for (int n = 0; n < 8; n++) {
            mr0 = fmaxf(mr0, fmaxf(s[n][0], s[n][1]));
            mr1 = fmaxf(mr1, fmaxf(s[n][2], s[n][3]));
        }
        mr0 = fmaxf(mr0, __shfl_xor_sync(0xffffffffu, mr0, 1));
        mr0 = fmaxf(mr0, __shfl_xor_sync(0xffffffffu, mr0, 2));
        mr1 = fmaxf(mr1, __shfl_xor_sync(0xffffffffu, mr1, 1));
        mr1 = fmaxf(mr1, __shfl_xor_sync(0xffffffffu, mr1, 2));

        float mn0 = fmaxf(m0, mr0), mn1 = fmaxf(m1, mr1);
        float a0 = exp2_approx(m0 - mn0), a1 = exp2_approx(m1 - mn1);
        m0 = mn0; m1 = mn1;
        l0 *= a0;  l1 *= a1;

        unsigned ph[8][2];
        float ls0 = 0.f, ls1 = 0.f;
        #pragma unroll
        for (int n = 0; n < 8; n++) {
            float p0 = exp2_approx(s[n][0] - mn0);
            float p1 = exp2_approx(s[n][1] - mn0);
            float p2 = exp2_approx(s[n][2] - mn1);
            float p3 = exp2_approx(s[n][3] - mn1);
            ls0 += p0 + p1; ls1 += p2 + p3;
            __half2 h01 = __floats2half2_rn(p0, p1);
            __half2 h23 = __floats2half2_rn(p2, p3);
            ph[n][0] = *reinterpret_cast<unsigned*>(&h01);
            ph[n][1] = *reinterpret_cast<unsigned*>(&h23);
        }
        l0 += ls0; l1 += ls1;
        #pragma unroll
        for (int n = 0; n < 8; n++) {
            o[n][0] *= a0; o[n][1] *= a0; o[n][2] *= a1; o[n][3] *= a1;
        }

        // O += P V  (4 k-steps over keys, 8 d-tiles)
        #pragma unroll
        for (int kv = 0; kv < 4; kv++) {
            unsigned pa[4] = { ph[2 * kv][0], ph[2 * kv][1],
                               ph[2 * kv + 1][0], ph[2 * kv + 1][1] };
            #pragma unroll
            for (int pv = 0; pv < 4; pv++) {
                unsigned vb[4];
                ldsm4t(vb, vAdr[kv] + vSw[pv]);
                mma16816(o[2 * pv],     pa, vb[0], vb[1]);
                mma16816(o[2 * pv + 1], pa, vb[2], vb[3]);
            }
        }
    }

    // epilogue: reduce l across quad, normalize, store
    l0 += __shfl_xor_sync(0xffffffffu, l0, 1);
    l0 += __shfl_xor_sync(0xffffffffu, l0, 2);
    l1 += __shfl_xor_sync(0xffffffffu, l1, 1);
    l1 += __shfl_xor_sync(0xffffffffu, l1, 2);
    float inv0 = 1.f / l0, inv1 = 1.f / l1;

    float* ob = out + ((long)b * Tn + qw) * HSn;
    #pragma unroll
    for (int n = 0; n < 8; n++) {
        float2 v0 = { o[n][0] * inv0, o[n][1] * inv0 };
        float2 v1 = { o[n][2] * inv1, o[n][3] * inv1 };
        *(float2*)(ob + (g    ) * HSn + n * 8 + 2 * t) = v0;
        *(float2*)(ob + (g + 8) * HSn + n * 8 + 2 * t) = v1;
    }
}

// ---------------------------------------------------------------------------
extern "C" void kernel_launch(void* const* d_in, const int* in_sizes, int n_in,
                              void* d_out, int out_size) {
    const float* x    = (const float*)d_in[0];
    const float* Wq   = (const float*)d_in[1];
    const float* Wk   = (const float*)d_in[2];
    const float* Wv   = (const float*)d_in[3];
    const float* fcos = (const float*)d_in[4];
    const float* fsin = (const float*)d_in[5];
    const int*   mask = (const int*)d_in[6];
    float* out = (float*)d_out;

    len_kernel<<<Bn, 256>>>(mask);
    qkv_kernel<<<Bn * Tn / 8, 128>>>(x, Wq, Wk, Wv, fcos, fsin);
    dim3 grid(Tn / 64, Bn);
    flash_kernel<<<grid, 128>>>(out);
}

// round 7
// speedup vs baseline: 10.9377x; 1.6742x over previous
#include <cuda_runtime.h>
#include <cuda_fp16.h>
#include <cstdint>
#include <stdint.h>

#define Bn 8
#define Tn 4096
#define Cn 128
#define HSn 64

// scale = 1/sqrt(C) folded with log2(e) so we can use ex2.approx
#define QSCALE (0.08838834764831845f * 1.4426950408889634f)

// Scratch (device globals — no allocation allowed in kernel_launch)
__device__ __align__(16) __half g_Q[Bn * Tn * HSn];
__device__ __align__(16) __half g_K[Bn * Tn * HSn];
__device__ __align__(16) __half g_V[Bn * Tn * HSn];
__device__ __align__(16) float  g_po[2 * Bn * Tn * HSn];  // unnormalized O partials
__device__ float g_pm[2 * Bn * Tn];
__device__ float g_pl[2 * Bn * Tn];
__device__ int g_len[Bn];

__device__ __forceinline__ float exp2_approx(float x) {
    float y;
    asm("ex2.approx.ftz.f32 %0, %1;" : "=f"(y) : "f"(x));
    return y;
}

__device__ __forceinline__ unsigned smem_u32(const void* p) {
    return (unsigned)__cvta_generic_to_shared(p);
}

__device__ __forceinline__ void mma16816(float* c, const unsigned* a,
                                         unsigned b0, unsigned b1) {
    asm volatile(
        "mma.sync.aligned.m16n8k16.row.col.f32.f16.f16.f32 "
        "{%0,%1,%2,%3}, {%4,%5,%6,%7}, {%8,%9}, {%0,%1,%2,%3};\n"
        : "+f"(c[0]), "+f"(c[1]), "+f"(c[2]), "+f"(c[3])
        : "r"(a[0]), "r"(a[1]), "r"(a[2]), "r"(a[3]), "r"(b0), "r"(b1));
}

__device__ __forceinline__ void ldsm4(unsigned* r, unsigned addr) {
    asm volatile("ldmatrix.sync.aligned.m8n8.x4.shared.b16 {%0,%1,%2,%3}, [%4];"
                 : "=r"(r[0]), "=r"(r[1]), "=r"(r[2]), "=r"(r[3]) : "r"(addr));
}

__device__ __forceinline__ void ldsm4t(unsigned* r, unsigned addr) {
    asm volatile("ldmatrix.sync.aligned.m8n8.x4.trans.shared.b16 {%0,%1,%2,%3}, [%4];"
                 : "=r"(r[0]), "=r"(r[1]), "=r"(r[2]), "=r"(r[3]) : "r"(addr));
}

// ---------------------------------------------------------------------------
// Kernel 0: per-batch valid length (mask is a prefix mask; length = sum)
// ---------------------------------------------------------------------------
__global__ void len_kernel(const int* __restrict__ mask) {
    int b = blockIdx.x;
    int tid = threadIdx.x;
    const int4* m4 = (const int4*)(mask + b * Tn);
    int sum = 0;
    #pragma unroll
    for (int i = 0; i < 4; i++) {
        int4 v = m4[tid + i * 256];
        sum += v.x + v.y + v.z + v.w;
    }
    __shared__ int red[8];
    #pragma unroll
    for (int off = 16; off > 0; off >>= 1)
        sum += __shfl_down_sync(0xffffffffu, sum, off);
    if ((tid & 31) == 0) red[tid >> 5] = sum;
    __syncthreads();
    if (tid == 0) {
        int s = 0;
        #pragma unroll
        for (int w = 0; w < 8; w++) s += red[w];
        g_len[b] = s;
    }
}

// ---------------------------------------------------------------------------
// Kernel 1: fused QKV projection + RoPE via HMMA.
// 12 warps: warp = (mat, row-group); each warp: 16 rows x 64 cols, K=128.
// W (fp16, swizzled) in 48KB smem as B-operand (ldsm4t); A-frags from gmem.
// ---------------------------------------------------------------------------
__global__ __launch_bounds__(384) void qkv_kernel(
    const float* __restrict__ x,
    const float* __restrict__ Wq,
    const float* __restrict__ Wk,
    const float* __restrict__ Wv,
    const float* __restrict__ fcos,
    const float* __restrict__ fsin)
{
    __shared__ __half Ws[3 * 128 * 64];     // 48KB: [mat][k=128][n=64], swizzled
    int tid = threadIdx.x;

    // cooperative W load + fp16 convert + swizzle (3072 16B-chunks)
    #pragma unroll
    for (int i = 0; i < 8; i++) {
        int cid = tid + i * 384;
        int mat = cid >> 10;
        int within = cid & 1023;
        int row = within >> 3, c = within & 7;
        const float* src = (mat == 0 ? Wq : (mat == 1 ? Wk : Wv)) + row * 64 + c * 8;
        float4 f0 = *(const float4*)src;
        float4 f1 = *(const float4*)(src + 4);
        union { __half2 h[4]; uint4 u; } pk;
        pk.h[0] = __floats2half2_rn(f0.x, f0.y);
        pk.h[1] = __floats2half2_rn(f0.z, f0.w);
        pk.h[2] = __floats2half2_rn(f1.x, f1.y);
        pk.h[3] = __floats2half2_rn(f1.z, f1.w);
        int dst = mat * 8192 + row * 64 + ((c ^ (row & 7)) * 8);
        *(uint4*)(Ws + dst) = pk.u;
    }
    __syncthreads();

    int w = tid >> 5, lane = tid & 31;
    int g = lane >> 2, tq = lane & 3;
    int mat = w >> 2, rg = w & 3;
    long rowa = (long)blockIdx.x * 64 + rg * 16 + g;

    float acc[8][4];
    #pragma unroll
    for (int n = 0; n < 8; n++) { acc[n][0] = acc[n][1] = acc[n][2] = acc[n][3] = 0.f; }

    unsigned wsb = smem_u32(Ws) + (unsigned)mat * 16384u;
    int grp = lane >> 3, r8 = lane & 7;
    unsigned wrow = (unsigned)(8 * (grp & 1) + r8) * 128u;
    unsigned wsw[4];
    #pragma unroll
    for (int pv = 0; pv < 4; pv++)
        wsw[pv] = (unsigned)(((2 * pv + (grp >> 1)) ^ r8) * 16);

    const float* xa = x + rowa * Cn;
    const float* xb = xa + 8 * Cn;

    #pragma unroll
    for (int ks = 0; ks < 8; ks++) {
        int off = ks * 16 + 2 * tq;
        float2 fa0 = *(const float2*)(xa + off);
        float2 fb0 = *(const float2*)(xb + off);
        float2 fa1 = *(const float2*)(xa + off + 8);
        float2 fb1 = *(const float2*)(xb + off + 8);
        union { __half2 h; unsigned u; } a0, a1, a2, a3;
        a0.h = __floats2half2_rn(fa0.x, fa0.y);
        a1.h = __floats2half2_rn(fb0.x, fb0.y);
        a2.h = __floats2half2_rn(fa1.x, fa1.y);
        a3.h = __floats2half2_rn(fb1.x, fb1.y);
        unsigned a[4] = { a0.u, a1.u, a2.u, a3.u };

        unsigned kbase = wsb + (unsigned)(16 * ks) * 128u + wrow;
        #pragma unroll
        for (int pv = 0; pv < 4; pv++) {
            unsigned wb[4];
            ldsm4t(wb, kbase + wsw[pv]);
            mma16816(acc[2 * pv],     a, wb[0], wb[1]);
            mma16816(acc[2 * pv + 1], a, wb[2], wb[3]);
        }
    }

    // epilogue: RoPE (Q,K) / passthrough (V), fp16 pack, store
    int ta = (int)(rowa & (Tn - 1));
    __half* dst = (mat == 0) ? g_Q : (mat == 1 ? g_K : g_V);
    long basea = rowa * HSn;
    long baseb = basea + 8 * HSn;

    if (mat <= 1) {
        float sc = (mat == 0) ? QSCALE : 1.f;
        const float* fca = fcos + (long)ta * 32;
        const float* fsa = fsin + (long)ta * 32;
        #pragma unroll
        for (int n = 0; n < 8; n++) {
            int p = n * 4 + tq;
            float ca = fca[p],       sa = fsa[p];
            float cb = fca[256 + p], sb = fsa[256 + p];   // token ta+8
            float c0 = acc[n][0] * sc, c1 = acc[n][1] * sc;
            float c2 = acc[n][2] * sc, c3 = acc[n][3] * sc;
            __half2 ra = __floats2half2_rn(c0 * ca - c1 * sa, c0 * sa + c1 * ca);
            __half2 rb = __floats2half2_rn(c2 * cb - c3 * sb, c2 * sb + c3 * cb);
            *(__half2*)(dst + basea + n * 8 + 2 * tq) = ra;
            *(__half2*)(dst + baseb + n * 8 + 2 * tq) = rb;
        }
    } else {
        #pragma unroll
        for (int n = 0; n < 8; n++) {
            __half2 ra = __floats2half2_rn(acc[n][0], acc[n][1]);
            __half2 rb = __floats2half2_rn(acc[n][2], acc[n][3]);
            *(__half2*)(dst + basea + n * 8 + 2 * tq) = ra;
            *(__half2*)(dst + baseb + n * 8 + 2 * tq) = rb;
        }
    }
}

// ---------------------------------------------------------------------------
// Kernel 2: flash attention (HMMA), split-K x2 for causal load balance.
// blockIdx.x = 2*qtile + half. Each half processes half the key tiles and
// writes unnormalized partials (o, m, l); merge_kernel recombines.
// ---------------------------------------------------------------------------
__global__ __launch_bounds__(128) void flash_kernel()
{
    __shared__ __half Ks[64 * HSn];
    __shared__ __half Vs[64 * HSn];

    int b = blockIdx.y;
    int j = blockIdx.x >> 1, half = blockIdx.x & 1;
    int q0 = j * 64;
    int tid = threadIdx.x, warp = tid >> 5, lane = tid & 31;
    int g = lane >> 2, t = lane & 3;
    int qw = q0 + warp * 16;
    int len = g_len[b];
    int kend = min(q0 + 64, len);
    int nt = (kend + 63) >> 6;
    int ti0 = half ? (nt >> 1) : 0;
    int ti1 = half ? nt : (nt >> 1);

    unsigned qf[4][4];
    {
        const __half* Qb = g_Q + ((long)b * Tn + qw) * HSn;
        #pragma unroll
        for (int ks = 0; ks < 4; ks++) {
            qf[ks][0] = *(const unsigned*)(Qb + (g    ) * HSn + ks * 16 + 2 * t);
            qf[ks][1] = *(const unsigned*)(Qb + (g + 8) * HSn + ks * 16 + 2 * t);
            qf[ks][2] = *(const unsigned*)(Qb + (g    ) * HSn + ks * 16 + 2 * t + 8);
            qf[ks][3] = *(const unsigned*)(Qb + (g + 8) * HSn + ks * 16 + 2 * t + 8);
        }
    }

    float o[8][4];
    #pragma unroll
    for (int n = 0; n < 8; n++) { o[n][0] = o[n][1] = o[n][2] = o[n][3] = 0.f; }
    float m0 = -1e30f, m1 = -1e30f, l0 = 0.f, l1 = 0.f;

    unsigned ksb = smem_u32(Ks), vsb = smem_u32(Vs);
    int grp = lane >> 3, r8 = lane & 7;
    unsigned kAdr[4], kSw[4], vAdr[4], vSw[4];
    #pragma unroll
    for (int p = 0; p < 4; p++)
        kAdr[p] = ksb + (unsigned)(16 * p + 8 * (grp >> 1) + r8) * 128u;
    #pragma unroll
    for (int ks = 0; ks < 4; ks++)
        kSw[ks] = (unsigned)(((2 * ks + (grp & 1)) ^ r8) * 16);
    #pragma unroll
    for (int kv = 0; kv < 4; kv++)
        vAdr[kv] = vsb + (unsigned)(16 * kv + 8 * (grp & 1) + r8) * 128u;
    #pragma unroll
    for (int pv = 0; pv < 4; pv++)
        vSw[pv] = (unsigned)(((2 * pv + (grp >> 1)) ^ r8) * 16);

    const __half* Kg = g_K + (long)b * Tn * HSn;
    const __half* Vg = g_V + (long)b * Tn * HSn;

    for (int ti = ti0; ti < ti1; ti++) {
        int kt = ti * 64;
        __syncthreads();
        #pragma unroll
        for (int i = 0; i < 4; i++) {
            int cid = tid + i * 128;
            int row = cid >> 3, c = cid & 7;
            uint4 k4 = *(const uint4*)(Kg + (long)(kt + row) * HSn + c * 8);
            uint4 v4 = *(const uint4*)(Vg + (long)(kt + row) * HSn + c * 8);
            int dst = row * HSn + ((c ^ (row & 7)) * 8);
            *(uint4*)(Ks + dst) = k4;
            *(uint4*)(Vs + dst) = v4;
        }
        __syncthreads();

        float s[8][4];
        #pragma unroll
        for (int n = 0; n < 8; n++) { s[n][0] = s[n][1] = s[n][2] = s[n][3] = 0.f; }
        #pragma unroll
        for (int ks = 0; ks < 4; ks++) {
            #pragma unroll
            for (int p = 0; p < 4; p++) {
                unsigned kb[4];
                ldsm4(kb, kAdr[p] + kSw[ks]);
                mma16816(s[2 * p],     qf[ks], kb[0], kb[1]);
                mma16816(s[2 * p + 1], qf[ks], kb[2], kb[3]);
            }
        }

        bool full = (kt + 63 <= qw) && (kt + 64 <= len);
        if (!full) {
            int rg = qw + g, rg8 = rg + 8;
            #pragma unroll
            for (int n = 0; n < 8; n++) {
                int k0 = kt + n * 8 + 2 * t;
                if (!(k0     <= rg  && k0     < len)) s[n][0] = -1e30f;
                if (!(k0 + 1 <= rg  && k0 + 1 < len)) s[n][1] = -1e30f;
                if (!(k0     <= rg8 && k0     < len)) s[n][2] = -1e30f;
                if (!(k0 + 1 <= rg8 && k0 + 1 < len)) s[n][3] = -1e30f;
            }
        }

        float mr0 = s[0][0], mr1 = s[0][2];
        #pragma unroll
        for (int n = 0; n < 8; n++) {
            mr0 = fmaxf(mr0, fmaxf(s[n][0], s[n][1]));
            mr1 = fmaxf(mr1, fmaxf(s[n][2], s[n][3]));
        }
        mr0 = fmaxf(mr0, __shfl_xor_sync(0xffffffffu, mr0, 1));
        mr0 = fmaxf(mr0, __shfl_xor_sync(0xffffffffu, mr0, 2));
        mr1 = fmaxf(mr1, __shfl_xor_sync(0xffffffffu, mr1, 1));
        mr1 = fmaxf(mr1, __shfl_xor_sync(0xffffffffu, mr1, 2));

        float mn0 = fmaxf(m0, mr0), mn1 = fmaxf(m1, mr1);
        float a0 = exp2_approx(m0 - mn0), a1 = exp2_approx(m1 - mn1);
        m0 = mn0; m1 = mn1;
        l0 *= a0;  l1 *= a1;

        unsigned ph[8][2];
        float ls0 = 0.f, ls1 = 0.f;
        #pragma unroll
        for (int n = 0; n < 8; n++) {
            float p0 = exp2_approx(s[n][0] - mn0);
            float p1 = exp2_approx(s[n][1] - mn0);
            float p2 = exp2_approx(s[n][2] - mn1);
            float p3 = exp2_approx(s[n][3] - mn1);
            ls0 += p0 + p1; ls1 += p2 + p3;
            __half2 h01 = __floats2half2_rn(p0, p1);
            __half2 h23 = __floats2half2_rn(p2, p3);
            ph[n][0] = *reinterpret_cast<unsigned*>(&h01);
            ph[n][1] = *reinterpret_cast<unsigned*>(&h23);
        }
        l0 += ls0; l1 += ls1;
        #pragma unroll
        for (int n = 0; n < 8; n++) {
            o[n][0] *= a0; o[n][1] *= a0; o[n][2] *= a1; o[n][3] *= a1;
        }

        #pragma unroll
        for (int kv = 0; kv < 4; kv++) {
            unsigned pa[4] = { ph[2 * kv][0], ph[2 * kv][1],
                               ph[2 * kv + 1][0], ph[2 * kv + 1][1] };
            #pragma unroll
            for (int pv = 0; pv < 4; pv++) {
                unsigned vb[4];
                ldsm4t(vb, vAdr[kv] + vSw[pv]);
                mma16816(o[2 * pv],     pa, vb[0], vb[1]);
                mma16816(o[2 * pv + 1], pa, vb[2], vb[3]);
            }
        }
    }

    // epilogue: reduce l across quad, store UNnormalized partials + (m,l)
    l0 += __shfl_xor_sync(0xffffffffu, l0, 1);
    l0 += __shfl_xor_sync(0xffffffffu, l0, 2);
    l1 += __shfl_xor_sync(0xffffffffu, l1, 1);
    l1 += __shfl_xor_sync(0xffffffffu, l1, 2);

    long rbase = (long)b * Tn + qw;                     // row index
    float* ob = g_po + ((long)half * Bn * Tn + rbase) * HSn;
    #pragma unroll
    for (int n = 0; n < 8; n++) {
        float2 v0 = { o[n][0], o[n][1] };
        float2 v1 = { o[n][2], o[n][3] };
        *(float2*)(ob + (g    ) * HSn + n * 8 + 2 * t) = v0;
        *(float2*)(ob + (g + 8) * HSn + n * 8 + 2 * t) = v1;
    }
    if (t == 0) {
        long pr = (long)half * Bn * Tn + rbase;
        g_pm[pr + g]     = m0;  g_pl[pr + g]     = l0;
        g_pm[pr + g + 8] = m1;  g_pl[pr + g + 8] = l1;
    }
}

// ---------------------------------------------------------------------------
// Kernel 3: merge the two split-K partials and normalize.
// 256 threads, 8 threads per row (8 floats each), 32 rows per block.
// ---------------------------------------------------------------------------
__global__ __launch_bounds__(256) void merge_kernel(float* __restrict__ out)
{
    int tid = threadIdx.x;
    long r = (long)blockIdx.x * 32 + (tid >> 3);
    int d0 = (tid & 7) * 8;

    float m0 = g_pm[r], l0 = g_pl[r];
    float m1 = g_pm[(long)Bn * Tn + r], l1 = g_pl[(long)Bn * Tn + r];
    float ms = fmaxf(m0, m1);
    float s0 = exp2_approx(m0 - ms);
    float s1 = exp2_approx(m1 - ms);
    float inv = 1.f / (l0 * s0 + l1 * s1);
    s0 *= inv; s1 *= inv;

    long base = r * HSn + d0;
    const float4* p0 = (const float4*)(g_po + base);
    const float4* p1 = (const float4*)(g_po + (long)Bn * Tn * HSn + base);
    float4* po = (float4*)(out + base);
    #pragma unroll
    for (int i = 0; i < 2; i++) {
        float4 a = p0[i], c = p1[i];
        float4 rr;
        rr.x = a.x * s0 + c.x * s1;
        rr.y = a.y * s0 + c.y * s1;
        rr.z = a.z * s0 + c.z * s1;
        rr.w = a.w * s0 + c.w * s1;
        po[i] = rr;
    }
}

// ---------------------------------------------------------------------------
extern "C" void kernel_launch(void* const* d_in, const int* in_sizes, int n_in,
                              void* d_out, int out_size) {
    const float* x    = (const float*)d_in[0];
    const float* Wq   = (const float*)d_in[1];
    const float* Wk   = (const float*)d_in[2];
    const float* Wv   = (const float*)d_in[3];
    const float* fcos = (const float*)d_in[4];
    const float* fsin = (const float*)d_in[5];
    const int*   mask = (const int*)d_in[6];
    float* out = (float*)d_out;

    len_kernel<<<Bn, 256>>>(mask);
    qkv_kernel<<<Bn * Tn / 64, 384>>>(x, Wq, Wk, Wv, fcos, fsin);
    dim3 grid(2 * Tn / 64, Bn);
    flash_kernel<<<grid, 128>>>();
    merge_kernel<<<Bn * Tn / 32, 256>>>(out);
}

// round 8
// speedup vs baseline: 11.1841x; 1.0225x over previous
#include <cuda_runtime.h>
#include <cuda_fp16.h>
#include <cstdint>
#include <stdint.h>

#define Bn 8
#define Tn 4096
#define Cn 128
#define HSn 64
#define BQ 128

// scale = 1/sqrt(C) folded with log2(e) so we can use ex2.approx
#define QSCALE (0.08838834764831845f * 1.4426950408889634f)

// Scratch (device globals — no allocation allowed in kernel_launch)
__device__ __align__(16) __half g_Q[Bn * Tn * HSn];
__device__ __align__(16) __half g_K[Bn * Tn * HSn];
__device__ __align__(16) __half g_V[Bn * Tn * HSn];
__device__ __align__(16) float  g_po[2 * Bn * Tn * HSn];  // unnormalized O partials
__device__ float g_pm[2 * Bn * Tn];
__device__ float g_pl[2 * Bn * Tn];
__device__ int g_len[Bn];

__device__ __forceinline__ float exp2_approx(float x) {
    float y;
    asm("ex2.approx.ftz.f32 %0, %1;" : "=f"(y) : "f"(x));
    return y;
}

__device__ __forceinline__ unsigned smem_u32(const void* p) {
    return (unsigned)__cvta_generic_to_shared(p);
}

__device__ __forceinline__ void mma16816(float* c, const unsigned* a,
                                         unsigned b0, unsigned b1) {
    asm volatile(
        "mma.sync.aligned.m16n8k16.row.col.f32.f16.f16.f32 "
        "{%0,%1,%2,%3}, {%4,%5,%6,%7}, {%8,%9}, {%0,%1,%2,%3};\n"
        : "+f"(c[0]), "+f"(c[1]), "+f"(c[2]), "+f"(c[3])
        : "r"(a[0]), "r"(a[1]), "r"(a[2]), "r"(a[3]), "r"(b0), "r"(b1));
}

__device__ __forceinline__ void ldsm4(unsigned* r, unsigned addr) {
    asm volatile("ldmatrix.sync.aligned.m8n8.x4.shared.b16 {%0,%1,%2,%3}, [%4];"
                 : "=r"(r[0]), "=r"(r[1]), "=r"(r[2]), "=r"(r[3]) : "r"(addr));
}

__device__ __forceinline__ void ldsm4t(unsigned* r, unsigned addr) {
    asm volatile("ldmatrix.sync.aligned.m8n8.x4.trans.shared.b16 {%0,%1,%2,%3}, [%4];"
                 : "=r"(r[0]), "=r"(r[1]), "=r"(r[2]), "=r"(r[3]) : "r"(addr));
}

__device__ __forceinline__ void cp_async16(unsigned dst, const void* src) {
    asm volatile("cp.async.cg.shared.global [%0], [%1], 16;\n"
                 :: "r"(dst), "l"(src));
}

__device__ __forceinline__ void cp_commit() {
    asm volatile("cp.async.commit_group;\n");
}

template <int N>
__device__ __forceinline__ void cp_wait() {
    asm volatile("cp.async.wait_group %0;\n" :: "n"(N));
}

// ---------------------------------------------------------------------------
// Kernel 0: per-batch valid length (mask is a prefix mask; length = sum)
// ---------------------------------------------------------------------------
__global__ void len_kernel(const int* __restrict__ mask) {
    int b = blockIdx.x;
    int tid = threadIdx.x;
    const int4* m4 = (const int4*)(mask + b * Tn);
    int sum = 0;
    #pragma unroll
    for (int i = 0; i < 4; i++) {
        int4 v = m4[tid + i * 256];
        sum += v.x + v.y + v.z + v.w;
    }
    __shared__ int red[8];
    #pragma unroll
    for (int off = 16; off > 0; off >>= 1)
        sum += __shfl_down_sync(0xffffffffu, sum, off);
    if ((tid & 31) == 0) red[tid >> 5] = sum;
    __syncthreads();
    if (tid == 0) {
        int s = 0;
        #pragma unroll
        for (int w = 0; w < 8; w++) s += red[w];
        g_len[b] = s;
    }
}

// ---------------------------------------------------------------------------
// Kernel 1: fused QKV projection + RoPE via HMMA.
// ---------------------------------------------------------------------------
__global__ __launch_bounds__(384) void qkv_kernel(
    const float* __restrict__ x,
    const float* __restrict__ Wq,
    const float* __restrict__ Wk,
    const float* __restrict__ Wv,
    const float* __restrict__ fcos,
    const float* __restrict__ fsin)
{
    __shared__ __half Ws[3 * 128 * 64];     // 48KB: [mat][k=128][n=64], swizzled
    int tid = threadIdx.x;

    #pragma unroll
    for (int i = 0; i < 8; i++) {
        int cid = tid + i * 384;
        int mat = cid >> 10;
        int within = cid & 1023;
        int row = within >> 3, c = within & 7;
        const float* src = (mat == 0 ? Wq : (mat == 1 ? Wk : Wv)) + row * 64 + c * 8;
        float4 f0 = *(const float4*)src;
        float4 f1 = *(const float4*)(src + 4);
        union { __half2 h[4]; uint4 u; } pk;
        pk.h[0] = __floats2half2_rn(f0.x, f0.y);
        pk.h[1] = __floats2half2_rn(f0.z, f0.w);
        pk.h[2] = __floats2half2_rn(f1.x, f1.y);
        pk.h[3] = __floats2half2_rn(f1.z, f1.w);
        int dst = mat * 8192 + row * 64 + ((c ^ (row & 7)) * 8);
        *(uint4*)(Ws + dst) = pk.u;
    }
    __syncthreads();

    int w = tid >> 5, lane = tid & 31;
    int g = lane >> 2, tq = lane & 3;
    int mat = w >> 2, rg = w & 3;
    long rowa = (long)blockIdx.x * 64 + rg * 16 + g;

    float acc[8][4];
    #pragma unroll
    for (int n = 0; n < 8; n++) { acc[n][0] = acc[n][1] = acc[n][2] = acc[n][3] = 0.f; }

    unsigned wsb = smem_u32(Ws) + (unsigned)mat * 16384u;
    int grp = lane >> 3, r8 = lane & 7;
    unsigned wrow = (unsigned)(8 * (grp & 1) + r8) * 128u;
    unsigned wsw[4];
    #pragma unroll
    for (int pv = 0; pv < 4; pv++)
        wsw[pv] = (unsigned)(((2 * pv + (grp >> 1)) ^ r8) * 16);

    const float* xa = x + rowa * Cn;
    const float* xb = xa + 8 * Cn;

    #pragma unroll
    for (int ks = 0; ks < 8; ks++) {
        int off = ks * 16 + 2 * tq;
        float2 fa0 = *(const float2*)(xa + off);
        float2 fb0 = *(const float2*)(xb + off);
        float2 fa1 = *(const float2*)(xa + off + 8);
        float2 fb1 = *(const float2*)(xb + off + 8);
        union { __half2 h; unsigned u; } a0, a1, a2, a3;
        a0.h = __floats2half2_rn(fa0.x, fa0.y);
        a1.h = __floats2half2_rn(fb0.x, fb0.y);
        a2.h = __floats2half2_rn(fa1.x, fa1.y);
        a3.h = __floats2half2_rn(fb1.x, fb1.y);
        unsigned a[4] = { a0.u, a1.u, a2.u, a3.u };

        unsigned kbase = wsb + (unsigned)(16 * ks) * 128u + wrow;
        #pragma unroll
        for (int pv = 0; pv < 4; pv++) {
            unsigned wb[4];
            ldsm4t(wb, kbase + wsw[pv]);
            mma16816(acc[2 * pv],     a, wb[0], wb[1]);
            mma16816(acc[2 * pv + 1], a, wb[2], wb[3]);
        }
    }

    int ta = (int)(rowa & (Tn - 1));
    __half* dst = (mat == 0) ? g_Q : (mat == 1 ? g_K : g_V);
    long basea = rowa * HSn;
    long baseb = basea + 8 * HSn;

    if (mat <= 1) {
        float sc = (mat == 0) ? QSCALE : 1.f;
        const float* fca = fcos + (long)ta * 32;
        const float* fsa = fsin + (long)ta * 32;
        #pragma unroll
        for (int n = 0; n < 8; n++) {
            int p = n * 4 + tq;
            float ca = fca[p],       sa = fsa[p];
            float cb = fca[256 + p], sb = fsa[256 + p];   // token ta+8
            float c0 = acc[n][0] * sc, c1 = acc[n][1] * sc;
            float c2 = acc[n][2] * sc, c3 = acc[n][3] * sc;
            __half2 ra = __floats2half2_rn(c0 * ca - c1 * sa, c0 * sa + c1 * ca);
            __half2 rb = __floats2half2_rn(c2 * cb - c3 * sb, c2 * sb + c3 * cb);
            *(__half2*)(dst + basea + n * 8 + 2 * tq) = ra;
            *(__half2*)(dst + baseb + n * 8 + 2 * tq) = rb;
        }
    } else {
        #pragma unroll
        for (int n = 0; n < 8; n++) {
            __half2 ra = __floats2half2_rn(acc[n][0], acc[n][1]);
            __half2 rb = __floats2half2_rn(acc[n][2], acc[n][3]);
            *(__half2*)(dst + basea + n * 8 + 2 * tq) = ra;
            *(__half2*)(dst + baseb + n * 8 + 2 * tq) = rb;
        }
    }
}

// ---------------------------------------------------------------------------
// Kernel 2: flash attention (HMMA), BQ=128 (8 warps), split-K x2,
// double-buffered cp.async K/V pipeline.
// ---------------------------------------------------------------------------
__global__ __launch_bounds__(256) void flash_kernel()
{
    __shared__ __half Ks[2][64 * HSn];
    __shared__ __half Vs[2][64 * HSn];

    int b = blockIdx.y;
    int j = blockIdx.x >> 1, half = blockIdx.x & 1;
    int q0 = j * BQ;
    int tid = threadIdx.x, warp = tid >> 5, lane = tid & 31;
    int g = lane >> 2, t = lane & 3;
    int qw = q0 + warp * 16;
    int len = g_len[b];
    int kend = min(q0 + BQ, len);
    int nt = (kend + 63) >> 6;
    int ti0 = half ? (nt >> 1) : 0;
    int ti1 = half ? nt : (nt >> 1);

    unsigned qf[4][4];
    {
        const __half* Qb = g_Q + ((long)b * Tn + qw) * HSn;
        #pragma unroll
        for (int ks = 0; ks < 4; ks++) {
            qf[ks][0] = *(const unsigned*)(Qb + (g    ) * HSn + ks * 16 + 2 * t);
            qf[ks][1] = *(const unsigned*)(Qb + (g + 8) * HSn + ks * 16 + 2 * t);
            qf[ks][2] = *(const unsigned*)(Qb + (g    ) * HSn + ks * 16 + 2 * t + 8);
            qf[ks][3] = *(const unsigned*)(Qb + (g + 8) * HSn + ks * 16 + 2 * t + 8);
        }
    }

    float o[8][4];
    #pragma unroll
    for (int n = 0; n < 8; n++) { o[n][0] = o[n][1] = o[n][2] = o[n][3] = 0.f; }
    float m0 = -1e30f, m1 = -1e30f, l0 = 0.f, l1 = 0.f;

    unsigned ksb = smem_u32(Ks), vsb = smem_u32(Vs);
    int grp = lane >> 3, r8 = lane & 7;
    unsigned kAdr[4], kSw[4], vAdr[4], vSw[4];
    #pragma unroll
    for (int p = 0; p < 4; p++)
        kAdr[p] = ksb + (unsigned)(16 * p + 8 * (grp >> 1) + r8) * 128u;
    #pragma unroll
    for (int ks = 0; ks < 4; ks++)
        kSw[ks] = (unsigned)(((2 * ks + (grp & 1)) ^ r8) * 16);
    #pragma unroll
    for (int kv = 0; kv < 4; kv++)
        vAdr[kv] = vsb + (unsigned)(16 * kv + 8 * (grp & 1) + r8) * 128u;
    #pragma unroll
    for (int pv = 0; pv < 4; pv++)
        vSw[pv] = (unsigned)(((2 * pv + (grp >> 1)) ^ r8) * 16);

    const __half* Kg = g_K + (long)b * Tn * HSn;
    const __half* Vg = g_V + (long)b * Tn * HSn;

    // cooperative loader: 1024 16B-chunks (512 K + 512 V), 4 per thread
    unsigned ks0 = ksb, vs0 = vsb;
    auto load_tile = [&](int buf, int kt) {
        unsigned bo = (unsigned)buf * 8192u;
        #pragma unroll
        for (int i = 0; i < 2; i++) {
            int cid = tid + i * 256;               // 0..511
            int row = cid >> 3, c = cid & 7;
            unsigned dst = (unsigned)(row * HSn + ((c ^ (row & 7)) * 8)) * 2u + bo;
            cp_async16(ks0 + dst, Kg + (long)(kt + row) * HSn + c * 8);
            cp_async16(vs0 + dst, Vg + (long)(kt + row) * HSn + c * 8);
        }
    };

    int buf = 0;
    if (ti0 < ti1) { load_tile(0, ti0 * 64); cp_commit(); }

    for (int ti = ti0; ti < ti1; ti++) {
        int kt = ti * 64;
        if (ti + 1 < ti1) {
            load_tile(buf ^ 1, (ti + 1) * 64);
            cp_commit();
            cp_wait<1>();
        } else {
            cp_wait<0>();
        }
        __syncthreads();

        unsigned bo = (unsigned)buf * 8192u;

        float s[8][4];
        #pragma unroll
        for (int n = 0; n < 8; n++) { s[n][0] = s[n][1] = s[n][2] = s[n][3] = 0.f; }
        #pragma unroll
        for (int ks = 0; ks < 4; ks++) {
            #pragma unroll
            for (int p = 0; p < 4; p++) {
                unsigned kb[4];
                ldsm4(kb, kAdr[p] + bo + kSw[ks]);
                mma16816(s[2 * p],     qf[ks], kb[0], kb[1]);
                mma16816(s[2 * p + 1], qf[ks], kb[2], kb[3]);
            }
        }

        bool full = (kt + 63 <= qw) && (kt + 64 <= len);
        if (!full) {
            int rg = qw + g, rg8 = rg + 8;
            #pragma unroll
            for (int n = 0; n < 8; n++) {
                int k0 = kt + n * 8 + 2 * t;
                if (!(k0     <= rg  && k0     < len)) s[n][0] = -1e30f;
                if (!(k0 + 1 <= rg  && k0 + 1 < len)) s[n][1] = -1e30f;
                if (!(k0     <= rg8 && k0     < len)) s[n][2] = -1e30f;
                if (!(k0 + 1 <= rg8 && k0 + 1 < len)) s[n][3] = -1e30f;
            }
        }

        float mr0 = s[0][0], mr1 = s[0][2];
        #pragma unroll
        for (int n = 0; n < 8; n++) {
            mr0 = fmaxf(mr0, fmaxf(s[n][0], s[n][1]));
            mr1 = fmaxf(mr1, fmaxf(s[n][2], s[n][3]));
        }
        mr0 = fmaxf(mr0, __shfl_xor_sync(0xffffffffu, mr0, 1));
        mr0 = fmaxf(mr0, __shfl_xor_sync(0xffffffffu, mr0, 2));
        mr1 = fmaxf(mr1, __shfl_xor_sync(0xffffffffu, mr1, 1));
        mr1 = fmaxf(mr1, __shfl_xor_sync(0xffffffffu, mr1, 2));

        float mn0 = fmaxf(m0, mr0), mn1 = fmaxf(m1, mr1);
        float a0 = exp2_approx(m0 - mn0), a1 = exp2_approx(m1 - mn1);
        m0 = mn0; m1 = mn1;
        l0 *= a0;  l1 *= a1;

        unsigned ph[8][2];
        float ls0 = 0.f, ls1 = 0.f;
        #pragma unroll
        for (int n = 0; n < 8; n++) {
            float p0 = exp2_approx(s[n][0] - mn0);
            float p1 = exp2_approx(s[n][1] - mn0);
            float p2 = exp2_approx(s[n][2] - mn1);
            float p3 = exp2_approx(s[n][3] - mn1);
            ls0 += p0 + p1; ls1 += p2 + p3;
            __half2 h01 = __floats2half2_rn(p0, p1);
            __half2 h23 = __floats2half2_rn(p2, p3);
            ph[n][0] = *reinterpret_cast<unsigned*>(&h01);
            ph[n][1] = *reinterpret_cast<unsigned*>(&h23);
        }
        l0 += ls0; l1 += ls1;
        #pragma unroll
        for (int n = 0; n < 8; n++) {
            o[n][0] *= a0; o[n][1] *= a0; o[n][2] *= a1; o[n][3] *= a1;
        }

        #pragma unroll
        for (int kv = 0; kv < 4; kv++) {
            unsigned pa[4] = { ph[2 * kv][0], ph[2 * kv][1],
                               ph[2 * kv + 1][0], ph[2 * kv + 1][1] };
            #pragma unroll
            for (int pv = 0; pv < 4; pv++) {
                unsigned vb[4];
                ldsm4t(vb, vAdr[kv] + bo + vSw[pv]);
                mma16816(o[2 * pv],     pa, vb[0], vb[1]);
                mma16816(o[2 * pv + 1], pa, vb[2], vb[3]);
            }
        }
        __syncthreads();   // all warps done with buf before it is overwritten
        buf ^= 1;
    }

    l0 += __shfl_xor_sync(0xffffffffu, l0, 1);
    l0 += __shfl_xor_sync(0xffffffffu, l0, 2);
    l1 += __shfl_xor_sync(0xffffffffu, l1, 1);
    l1 += __shfl_xor_sync(0xffffffffu, l1, 2);

    long rbase = (long)b * Tn + qw;
    float* ob = g_po + ((long)half * Bn * Tn + rbase) * HSn;
    #pragma unroll
    for (int n = 0; n < 8; n++) {
        float2 v0 = { o[n][0], o[n][1] };
        float2 v1 = { o[n][2], o[n][3] };
        *(float2*)(ob + (g    ) * HSn + n * 8 + 2 * t) = v0;
        *(float2*)(ob + (g + 8) * HSn + n * 8 + 2 * t) = v1;
    }
    if (t == 0) {
        long pr = (long)half * Bn * Tn + rbase;
        g_pm[pr + g]     = m0;  g_pl[pr + g]     = l0;
        g_pm[pr + g + 8] = m1;  g_pl[pr + g + 8] = l1;
    }
}

// ---------------------------------------------------------------------------
// Kernel 3: merge the two split-K partials and normalize.
// ---------------------------------------------------------------------------
__global__ __launch_bounds__(256) void merge_kernel(float* __restrict__ out)
{
    int tid = threadIdx.x;
    long r = (long)blockIdx.x * 32 + (tid >> 3);
    int d0 = (tid & 7) * 8;

    float m0 = g_pm[r], l0 = g_pl[r];
    float m1 = g_pm[(long)Bn * Tn + r], l1 = g_pl[(long)Bn * Tn + r];
    float ms = fmaxf(m0, m1);
    float s0 = exp2_approx(m0 - ms);
    float s1 = exp2_approx(m1 - ms);
    float inv = 1.f / (l0 * s0 + l1 * s1);
    s0 *= inv; s1 *= inv;

    long base = r * HSn + d0;
    const float4* p0 = (const float4*)(g_po + base);
    const float4* p1 = (const float4*)(g_po + (long)Bn * Tn * HSn + base);
    float4* po = (float4*)(out + base);
    #pragma unroll
    for (int i = 0; i < 2; i++) {
        float4 a = p0[i], c = p1[i];
        float4 rr;
        rr.x = a.x * s0 + c.x * s1;
        rr.y = a.y * s0 + c.y * s1;
        rr.z = a.z * s0 + c.z * s1;
        rr.w = a.w * s0 + c.w * s1;
        po[i] = rr;
    }
}

// ---------------------------------------------------------------------------
extern "C" void kernel_launch(void* const* d_in, const int* in_sizes, int n_in,
                              void* d_out, int out_size) {
    const float* x    = (const float*)d_in[0];
    const float* Wq   = (const float*)d_in[1];
    const float* Wk   = (const float*)d_in[2];
    const float* Wv   = (const float*)d_in[3];
    const float* fcos = (const float*)d_in[4];
    const float* fsin = (const float*)d_in[5];
    const int*   mask = (const int*)d_in[6];
    float* out = (float*)d_out;

    len_kernel<<<Bn, 256>>>(mask);
    qkv_kernel<<<Bn * Tn / 64, 384>>>(x, Wq, Wk, Wv, fcos, fsin);
    dim3 grid(2 * Tn / BQ, Bn);
    flash_kernel<<<grid, 256>>>();
    merge_kernel<<<Bn * Tn / 32, 256>>>(out);
}

// round 10
// speedup vs baseline: 11.2077x; 1.0021x over previous
#include <cuda_runtime.h>
#include <cuda_fp16.h>
#include <cstdint>
#include <stdint.h>

#define Bn 8
#define Tn 4096
#define Cn 128
#define HSn 64
#define BQ 128

// scale = 1/sqrt(C) folded with log2(e) so we can use ex2.approx
#define QSCALE (0.08838834764831845f * 1.4426950408889634f)

// Scratch (device globals — no allocation allowed in kernel_launch)
__device__ __align__(16) __half g_Q[Bn * Tn * HSn];
__device__ __align__(16) __half g_K[Bn * Tn * HSn];
__device__ __align__(16) __half g_V[Bn * Tn * HSn];
__device__ __align__(16) float  g_po[2 * Bn * Tn * HSn];  // unnormalized O partials
__device__ float g_pm[2 * Bn * Tn];
__device__ float g_pl[2 * Bn * Tn];
__device__ int g_len[Bn];

__device__ __forceinline__ float exp2_approx(float x) {
    float y;
    asm("ex2.approx.ftz.f32 %0, %1;" : "=f"(y) : "f"(x));
    return y;
}

__device__ __forceinline__ unsigned exp2_h2(unsigned x) {
    unsigned y;
    asm("ex2.approx.f16x2 %0, %1;" : "=r"(y) : "r"(x));
    return y;
}

__device__ __forceinline__ unsigned smem_u32(const void* p) {
    return (unsigned)__cvta_generic_to_shared(p);
}

// fp32-accum HMMA (qkv kernel)
__device__ __forceinline__ void mma16816(float* c, const unsigned* a,
                                         unsigned b0, unsigned b1) {
    asm volatile(
        "mma.sync.aligned.m16n8k16.row.col.f32.f16.f16.f32 "
        "{%0,%1,%2,%3}, {%4,%5,%6,%7}, {%8,%9}, {%0,%1,%2,%3};\n"
        : "+f"(c[0]), "+f"(c[1]), "+f"(c[2]), "+f"(c[3])
        : "r"(a[0]), "r"(a[1]), "r"(a[2]), "r"(a[3]), "r"(b0), "r"(b1));
}

// fp16-accum HMMA (flash kernel) — 2x rate, C fragment == A fragment layout
__device__ __forceinline__ void mma16816h(unsigned* c, const unsigned* a,
                                          unsigned b0, unsigned b1) {
    asm volatile(
        "mma.sync.aligned.m16n8k16.row.col.f16.f16.f16.f16 "
        "{%0,%1}, {%2,%3,%4,%5}, {%6,%7}, {%0,%1};\n"
        : "+r"(c[0]), "+r"(c[1])
        : "r"(a[0]), "r"(a[1]), "r"(a[2]), "r"(a[3]), "r"(b0), "r"(b1));
}

__device__ __forceinline__ void ldsm4(unsigned* r, unsigned addr) {
    asm volatile("ldmatrix.sync.aligned.m8n8.x4.shared.b16 {%0,%1,%2,%3}, [%4];"
                 : "=r"(r[0]), "=r"(r[1]), "=r"(r[2]), "=r"(r[3]) : "r"(addr));
}

__device__ __forceinline__ void ldsm4t(unsigned* r, unsigned addr) {
    asm volatile("ldmatrix.sync.aligned.m8n8.x4.trans.shared.b16 {%0,%1,%2,%3}, [%4];"
                 : "=r"(r[0]), "=r"(r[1]), "=r"(r[2]), "=r"(r[3]) : "r"(addr));
}

__device__ __forceinline__ void cp_async16(unsigned dst, const void* src) {
    asm volatile("cp.async.cg.shared.global [%0], [%1], 16;\n"
                 :: "r"(dst), "l"(src));
}
__device__ __forceinline__ void cp_commit() {
    asm volatile("cp.async.commit_group;\n");
}
template <int N>
__device__ __forceinline__ void cp_wait() {
    asm volatile("cp.async.wait_group %0;\n" :: "n"(N));
}

// ---------------------------------------------------------------------------
// Kernel 0: per-batch valid length (mask is a prefix mask; length = sum)
// ---------------------------------------------------------------------------
__global__ void len_kernel(const int* __restrict__ mask) {
    int b = blockIdx.x;
    int tid = threadIdx.x;
    const int4* m4 = (const int4*)(mask + b * Tn);
    int sum = 0;
    #pragma unroll
    for (int i = 0; i < 4; i++) {
        int4 v = m4[tid + i * 256];
        sum += v.x + v.y + v.z + v.w;
    }
    __shared__ int red[8];
    #pragma unroll
    for (int off = 16; off > 0; off >>= 1)
        sum += __shfl_down_sync(0xffffffffu, sum, off);
    if ((tid & 31) == 0) red[tid >> 5] = sum;
    __syncthreads();
    if (tid == 0) {
        int s = 0;
        #pragma unroll
        for (int w = 0; w < 8; w++) s += red[w];
        g_len[b] = s;
    }
}

// ---------------------------------------------------------------------------
// Kernel 1: fused QKV projection + RoPE via HMMA (fp32 accum for accuracy).
// ---------------------------------------------------------------------------
__global__ __launch_bounds__(384) void qkv_kernel(
    const float* __restrict__ x,
    const float* __restrict__ Wq,
    const float* __restrict__ Wk,
    const float* __restrict__ Wv,
    const float* __restrict__ fcos,
    const float* __restrict__ fsin)
{
    __shared__ __half Ws[3 * 128 * 64];     // 48KB: [mat][k=128][n=64], swizzled
    int tid = threadIdx.x;

    #pragma unroll
    for (int i = 0; i < 8; i++) {
        int cid = tid + i * 384;
        int mat = cid >> 10;
        int within = cid & 1023;
        int row = within >> 3, c = within & 7;
        const float* src = (mat == 0 ? Wq : (mat == 1 ? Wk : Wv)) + row * 64 + c * 8;
        float4 f0 = *(const float4*)src;
        float4 f1 = *(const float4*)(src + 4);
        union { __half2 h[4]; uint4 u; } pk;
        pk.h[0] = __floats2half2_rn(f0.x, f0.y);
        pk.h[1] = __floats2half2_rn(f0.z, f0.w);
        pk.h[2] = __floats2half2_rn(f1.x, f1.y);
        pk.h[3] = __floats2half2_rn(f1.z, f1.w);
        int dst = mat * 8192 + row * 64 + ((c ^ (row & 7)) * 8);
        *(uint4*)(Ws + dst) = pk.u;
    }
    __syncthreads();

    int w = tid >> 5, lane = tid & 31;
    int g = lane >> 2, tq = lane & 3;
    int mat = w >> 2, rg = w & 3;
    long rowa = (long)blockIdx.x * 64 + rg * 16 + g;

    float acc[8][4];
    #pragma unroll
    for (int n = 0; n < 8; n++) { acc[n][0] = acc[n][1] = acc[n][2] = acc[n][3] = 0.f; }

    unsigned wsb = smem_u32(Ws) + (unsigned)mat * 16384u;
    int grp = lane >> 3, r8 = lane & 7;
    unsigned wrow = (unsigned)(8 * (grp & 1) + r8) * 128u;
    unsigned wsw[4];
    #pragma unroll
    for (int pv = 0; pv < 4; pv++)
        wsw[pv] = (unsigned)(((2 * pv + (grp >> 1)) ^ r8) * 16);

    const float* xa = x + rowa * Cn;
    const float* xb = xa + 8 * Cn;

    #pragma unroll
    for (int ks = 0; ks < 8; ks++) {
        int off = ks * 16 + 2 * tq;
        float2 fa0 = *(const float2*)(xa + off);
        float2 fb0 = *(const float2*)(xb + off);
        float2 fa1 = *(const float2*)(xa + off + 8);
        float2 fb1 = *(const float2*)(xb + off + 8);
        union { __half2 h; unsigned u; } a0, a1, a2, a3;
        a0.h = __floats2half2_rn(fa0.x, fa0.y);
        a1.h = __floats2half2_rn(fb0.x, fb0.y);
        a2.h = __floats2half2_rn(fa1.x, fa1.y);
        a3.h = __floats2half2_rn(fb1.x, fb1.y);
        unsigned a[4] = { a0.u, a1.u, a2.u, a3.u };

        unsigned kbase = wsb + (unsigned)(16 * ks) * 128u + wrow;
        #pragma unroll
        for (int pv = 0; pv < 4; pv++) {
            unsigned wb[4];
            ldsm4t(wb, kbase + wsw[pv]);
            mma16816(acc[2 * pv],     a, wb[0], wb[1]);
            mma16816(acc[2 * pv + 1], a, wb[2], wb[3]);
        }
    }

    int ta = (int)(rowa & (Tn - 1));
    __half* dst = (mat == 0) ? g_Q : (mat == 1 ? g_K : g_V);
    long basea = rowa * HSn;
    long baseb = basea + 8 * HSn;

    if (mat <= 1) {
        float sc = (mat == 0) ? QSCALE : 1.f;
        const float* fca = fcos + (long)ta * 32;
        const float* fsa = fsin + (long)ta * 32;
        #pragma unroll
        for (int n = 0; n < 8; n++) {
            int p = n * 4 + tq;
            float ca = fca[p],       sa = fsa[p];
            float cb = fca[256 + p], sb = fsa[256 + p];   // token ta+8
            float c0 = acc[n][0] * sc, c1 = acc[n][1] * sc;
            float c2 = acc[n][2] * sc, c3 = acc[n][3] * sc;
            __half2 ra = __floats2half2_rn(c0 * ca - c1 * sa, c0 * sa + c1 * ca);
            __half2 rb = __floats2half2_rn(c2 * cb - c3 * sb, c2 * sb + c3 * cb);
            *(__half2*)(dst + basea + n * 8 + 2 * tq) = ra;
            *(__half2*)(dst + baseb + n * 8 + 2 * tq) = rb;
        }
    } else {
        #pragma unroll
        for (int n = 0; n < 8; n++) {
            __half2 ra = __floats2half2_rn(acc[n][0], acc[n][1]);
            __half2 rb = __floats2half2_rn(acc[n][2], acc[n][3]);
            *(__half2*)(dst + basea + n * 8 + 2 * tq) = ra;
            *(__half2*)(dst + baseb + n * 8 + 2 * tq) = rb;
        }
    }
}

// ---------------------------------------------------------------------------
// Kernel 2: flash attention, fp16-accum HMMA (2x rate), BQ=128 (8 warps),
// split-K x2, double-buffered cp.async K/V pipeline.
// S fragments (f16 C) are exp'd in-place via ex2.approx.f16x2 and reused
// directly as the P A-operand — zero repack.
// ---------------------------------------------------------------------------
__global__ __launch_bounds__(256) void flash_kernel()
{
    __shared__ __half Ks[2][64 * HSn];
    __shared__ __half Vs[2][64 * HSn];

    int b = blockIdx.y;
    int j = blockIdx.x >> 1, half = blockIdx.x & 1;
    int q0 = j * BQ;
    int tid = threadIdx.x, warp = tid >> 5, lane = tid & 31;
    int g = lane >> 2, t = lane & 3;
    int qw = q0 + warp * 16;
    int len = g_len[b];
    int kend = min(q0 + BQ, len);
    int nt = (kend + 63) >> 6;
    int ti0 = half ? (nt >> 1) : 0;
    int ti1 = half ? nt : (nt >> 1);

    unsigned qf[4][4];
    {
        const __half* Qb = g_Q + ((long)b * Tn + qw) * HSn;
        #pragma unroll
        for (int ks = 0; ks < 4; ks++) {
            qf[ks][0] = *(const unsigned*)(Qb + (g    ) * HSn + ks * 16 + 2 * t);
            qf[ks][1] = *(const unsigned*)(Qb + (g + 8) * HSn + ks * 16 + 2 * t);
            qf[ks][2] = *(const unsigned*)(Qb + (g    ) * HSn + ks * 16 + 2 * t + 8);
            qf[ks][3] = *(const unsigned*)(Qb + (g + 8) * HSn + ks * 16 + 2 * t + 8);
        }
    }

    float o[8][4];
    #pragma unroll
    for (int n = 0; n < 8; n++) { o[n][0] = o[n][1] = o[n][2] = o[n][3] = 0.f; }
    float m0 = -1e30f, m1 = -1e30f, l0 = 0.f, l1 = 0.f;

    unsigned ksb = smem_u32(Ks), vsb = smem_u32(Vs);
    int grp = lane >> 3, r8 = lane & 7;
    unsigned kAdr[4], kSw[4], vAdr[4], vSw[4];
    #pragma unroll
    for (int p = 0; p < 4; p++)
        kAdr[p] = ksb + (unsigned)(16 * p + 8 * (grp >> 1) + r8) * 128u;
    #pragma unroll
    for (int ks = 0; ks < 4; ks++)
        kSw[ks] = (unsigned)(((2 * ks + (grp & 1)) ^ r8) * 16);
    #pragma unroll
    for (int kv = 0; kv < 4; kv++)
        vAdr[kv] = vsb + (unsigned)(16 * kv + 8 * (grp & 1) + r8) * 128u;
    #pragma unroll
    for (int pv = 0; pv < 4; pv++)
        vSw[pv] = (unsigned)(((2 * pv + (grp >> 1)) ^ r8) * 16);

    const __half* Kg = g_K + (long)b * Tn * HSn;
    const __half* Vg = g_V + (long)b * Tn * HSn;

    auto load_tile = [&](int bu, int kt) {
        unsigned bo = (unsigned)bu * 8192u;
        #pragma unroll
        for (int i = 0; i < 2; i++) {
            int cid = tid + i * 256;               // 0..511
            int row = cid >> 3, c = cid & 7;
            unsigned dst = (unsigned)(row * HSn + ((c ^ (row & 7)) * 8)) * 2u + bo;
            cp_async16(ksb + dst, Kg + (long)(kt + row) * HSn + c * 8);
            cp_async16(vsb + dst, Vg + (long)(kt + row) * HSn + c * 8);
        }
    };

    const __half HM = __float2half_rn(-60000.f);   // finite mask; exp2 underflows to 0

    int buf = 0;
    if (ti0 < ti1) { load_tile(0, ti0 * 64); cp_commit(); }

    for (int ti = ti0; ti < ti1; ti++) {
        int kt = ti * 64;
        if (ti + 1 < ti1) {
            load_tile(buf ^ 1, (ti + 1) * 64);
            cp_commit();
            cp_wait<1>();
        } else {
            cp_wait<0>();
        }
        __syncthreads();

        unsigned bo = (unsigned)buf * 8192u;

        // S = Q K^T in fp16 accum: sreg[n] = {row g half2, row g+8 half2}
        unsigned sreg[8][2];
        #pragma unroll
        for (int n = 0; n < 8; n++) { sreg[n][0] = 0u; sreg[n][1] = 0u; }
        #pragma unroll
        for (int ks = 0; ks < 4; ks++) {
            #pragma unroll
            for (int p = 0; p < 4; p++) {
                unsigned kb[4];
                ldsm4(kb, kAdr[p] + bo + kSw[ks]);
                mma16816h(sreg[2 * p],     qf[ks], kb[0], kb[1]);
                mma16816h(sreg[2 * p + 1], qf[ks], kb[2], kb[3]);
            }
        }

        // mask (only diagonal / tail tiles)
        bool full = (kt + 63 <= qw) && (kt + 64 <= len);
        if (!full) {
            int rg = qw + g, rg8 = rg + 8;
            #pragma unroll
            for (int n = 0; n < 8; n++) {
                int k0 = kt + n * 8 + 2 * t;
                __half2 v0 = *reinterpret_cast<__half2*>(&sreg[n][0]);
                __half2 v1 = *reinterpret_cast<__half2*>(&sreg[n][1]);
                if (!(k0     <= rg  && k0     < len)) v0.x = HM;
                if (!(k0 + 1 <= rg  && k0 + 1 < len)) v0.y = HM;
                if (!(k0     <= rg8 && k0     < len)) v1.x = HM;
                if (!(k0 + 1 <= rg8 && k0 + 1 < len)) v1.y = HM;
                sreg[n][0] = *reinterpret_cast<unsigned*>(&v0);
                sreg[n][1] = *reinterpret_cast<unsigned*>(&v1);
            }
        }

        // row max via half2 trees (rows g and g+8), finalize fp32
        {
            __half2 h0 = *reinterpret_cast<__half2*>(&sreg[0][0]);
            __half2 h1 = *reinterpret_cast<__half2*>(&sreg[0][1]);
            #pragma unroll
            for (int n = 1; n < 8; n++) {
                h0 = __hmax2(h0, *reinterpret_cast<__half2*>(&sreg[n][0]));
                h1 = __hmax2(h1, *reinterpret_cast<__half2*>(&sreg[n][1]));
            }
            float2 f0 = __half22float2(h0);
            float2 f1 = __half22float2(h1);
            float mr0 = fmaxf(f0.x, f0.y);
            float mr1 = fmaxf(f1.x, f1.y);
            mr0 = fmaxf(mr0, __shfl_xor_sync(0xffffffffu, mr0, 1));
            mr0 = fmaxf(mr0, __shfl_xor_sync(0xffffffffu, mr0, 2));
            mr1 = fmaxf(mr1, __shfl_xor_sync(0xffffffffu, mr1, 1));
            mr1 = fmaxf(mr1, __shfl_xor_sync(0xffffffffu, mr1, 2));

            float mn0 = fmaxf(m0, mr0), mn1 = fmaxf(m1, mr1);
            float a0 = exp2_approx(m0 - mn0), a1 = exp2_approx(m1 - mn1);
            m0 = mn0; m1 = mn1;
            l0 *= a0;  l1 *= a1;

            // p = exp2(s - mn) in-place (f16x2) -> directly the PV A-operand
            __half2 mh0 = __float2half2_rn(mn0);
            __half2 mh1 = __float2half2_rn(mn1);
            float ls0 = 0.f, ls1 = 0.f;
            #pragma unroll
            for (int n = 0; n < 8; n++) {
                __half2 d0 = __hsub2(*reinterpret_cast<__half2*>(&sreg[n][0]), mh0);
                __half2 d1 = __hsub2(*reinterpret_cast<__half2*>(&sreg[n][1]), mh1);
                sreg[n][0] = exp2_h2(*reinterpret_cast<unsigned*>(&d0));
                sreg[n][1] = exp2_h2(*reinterpret_cast<unsigned*>(&d1));
                float2 p0 = __half22float2(*reinterpret_cast<__half2*>(&sreg[n][0]));
                float2 p1 = __half22float2(*reinterpret_cast<__half2*>(&sreg[n][1]));
                ls0 += p0.x + p0.y;
                ls1 += p1.x + p1.y;
            }
            l0 += ls0; l1 += ls1;

            // O += P V  (fp16 accum per tile, fp32 carry across tiles)
            unsigned dreg[8][2];
            #pragma unroll
            for (int n = 0; n < 8; n++) { dreg[n][0] = 0u; dreg[n][1] = 0u; }
            #pragma unroll
            for (int kv = 0; kv < 4; kv++) {
                unsigned pa[4] = { sreg[2 * kv][0], sreg[2 * kv][1],
                                   sreg[2 * kv + 1][0], sreg[2 * kv + 1][1] };
                #pragma unroll
                for (int pv = 0; pv < 4; pv++) {
                    unsigned vb[4];
                    ldsm4t(vb, vAdr[kv] + bo + vSw[pv]);
                    mma16816h(dreg[2 * pv],     pa, vb[0], vb[1]);
                    mma16816h(dreg[2 * pv + 1], pa, vb[2], vb[3]);
                }
            }
            #pragma unroll
            for (int n = 0; n < 8; n++) {
                float2 d0 = __half22float2(*reinterpret_cast<__half2*>(&dreg[n][0]));
                float2 d1 = __half22float2(*reinterpret_cast<__half2*>(&dreg[n][1]));
                o[n][0] = o[n][0] * a0 + d0.x;
                o[n][1] = o[n][1] * a0 + d0.y;
                o[n][2] = o[n][2] * a1 + d1.x;
                o[n][3] = o[n][3] * a1 + d1.y;
            }
        }
        __syncthreads();   // all warps done with buf before it is overwritten
        buf ^= 1;
    }

    l0 += __shfl_xor_sync(0xffffffffu, l0, 1);
    l0 += __shfl_xor_sync(0xffffffffu, l0, 2);
    l1 += __shfl_xor_sync(0xffffffffu, l1, 1);
    l1 += __shfl_xor_sync(0xffffffffu, l1, 2);

    long rbase = (long)b * Tn + qw;
    float* ob = g_po + ((long)half * Bn * Tn + rbase) * HSn;
    #pragma unroll
    for (int n = 0; n < 8; n++) {
        float2 v0 = { o[n][0], o[n][1] };
        float2 v1 = { o[n][2], o[n][3] };
        *(float2*)(ob + (g    ) * HSn + n * 8 + 2 * t) = v0;
        *(float2*)(ob + (g + 8) * HSn + n * 8 + 2 * t) = v1;
    }
    if (t == 0) {
        long pr = (long)half * Bn * Tn + rbase;
        g_pm[pr + g]     = m0;  g_pl[pr + g]     = l0;
        g_pm[pr + g + 8] = m1;  g_pl[pr + g + 8] = l1;
    }
}

// ---------------------------------------------------------------------------
// Kernel 3: merge the two split-K partials and normalize.
// ---------------------------------------------------------------------------
__global__ __launch_bounds__(256) void merge_kernel(float* __restrict__ out)
{
    int tid = threadIdx.x;
    long r = (long)blockIdx.x * 32 + (tid >> 3);
    int d0 = (tid & 7) * 8;

    float m0 = g_pm[r], l0 = g_pl[r];
    float m1 = g_pm[(long)Bn * Tn + r], l1 = g_pl[(long)Bn * Tn + r];
    float ms = fmaxf(m0, m1);
    float s0 = exp2_approx(m0 - ms);
    float s1 = exp2_approx(m1 - ms);
    float inv = 1.f / (l0 * s0 + l1 * s1);
    s0 *= inv; s1 *= inv;

    long base = r * HSn + d0;
    const float4* p0 = (const float4*)(g_po + base);
    const float4* p1 = (const float4*)(g_po + (long)Bn * Tn * HSn + base);
    float4* po = (float4*)(out + base);
    #pragma unroll
    for (int i = 0; i < 2; i++) {
        float4 a = p0[i], c = p1[i];
        float4 rr;
        rr.x = a.x * s0 + c.x * s1;
        rr.y = a.y * s0 + c.y * s1;
        rr.z = a.z * s0 + c.z * s1;
        rr.w = a.w * s0 + c.w * s1;
        po[i] = rr;
    }
}

// ---------------------------------------------------------------------------
extern "C" void kernel_launch(void* const* d_in, const int* in_sizes, int n_in,
                              void* d_out, int out_size) {
    const float* x    = (const float*)d_in[0];
    const float* Wq   = (const float*)d_in[1];
    const float* Wk   = (const float*)d_in[2];
    const float* Wv   = (const float*)d_in[3];
    const float* fcos = (const float*)d_in[4];
    const float* fsin = (const float*)d_in[5];
    const int*   mask = (const int*)d_in[6];
    float* out = (float*)d_out;

    len_kernel<<<Bn, 256>>>(mask);
    qkv_kernel<<<Bn * Tn / 64, 384>>>(x, Wq, Wk, Wv, fcos, fsin);
    dim3 grid(2 * Tn / BQ, Bn);
    flash_kernel<<<grid, 256>>>();
    merge_kernel<<<Bn * Tn / 32, 256>>>(out);
}

// round 11
// speedup vs baseline: 11.3133x; 1.0094x over previous
#include <cuda_runtime.h>
#include <cuda_fp16.h>
#include <cstdint>
#include <stdint.h>

#define Bn 8
#define Tn 4096
#define Cn 128
#define HSn 64
#define BQ 128

// scale = 1/sqrt(C) folded with log2(e) so we can use ex2.approx
#define QSCALE (0.08838834764831845f * 1.4426950408889634f)

// Scratch (device globals — no allocation allowed in kernel_launch)
__device__ __align__(16) __half g_Q[Bn * Tn * HSn];
__device__ __align__(16) __half g_K[Bn * Tn * HSn];
__device__ __align__(16) __half g_V[Bn * Tn * HSn];
__device__ __align__(16) float  g_po[2 * Bn * Tn * HSn];  // unnormalized O partials
__device__ float g_pm[2 * Bn * Tn];
__device__ float g_pl[2 * Bn * Tn];
__device__ int g_len[Bn];

__device__ __forceinline__ float exp2_approx(float x) {
    float y;
    asm("ex2.approx.ftz.f32 %0, %1;" : "=f"(y) : "f"(x));
    return y;
}

__device__ __forceinline__ unsigned exp2_h2(unsigned x) {
    unsigned y;
    asm("ex2.approx.f16x2 %0, %1;" : "=r"(y) : "r"(x));
    return y;
}

__device__ __forceinline__ unsigned smem_u32(const void* p) {
    return (unsigned)__cvta_generic_to_shared(p);
}

// fp32-accum HMMA (qkv kernel)
__device__ __forceinline__ void mma16816(float* c, const unsigned* a,
                                         unsigned b0, unsigned b1) {
    asm volatile(
        "mma.sync.aligned.m16n8k16.row.col.f32.f16.f16.f32 "
        "{%0,%1,%2,%3}, {%4,%5,%6,%7}, {%8,%9}, {%0,%1,%2,%3};\n"
        : "+f"(c[0]), "+f"(c[1]), "+f"(c[2]), "+f"(c[3])
        : "r"(a[0]), "r"(a[1]), "r"(a[2]), "r"(a[3]), "r"(b0), "r"(b1));
}

// fp16-accum HMMA (flash kernel) — C fragment == A fragment layout
__device__ __forceinline__ void mma16816h(unsigned* c, const unsigned* a,
                                          unsigned b0, unsigned b1) {
    asm volatile(
        "mma.sync.aligned.m16n8k16.row.col.f16.f16.f16.f16 "
        "{%0,%1}, {%2,%3,%4,%5}, {%6,%7}, {%0,%1};\n"
        : "+r"(c[0]), "+r"(c[1])
        : "r"(a[0]), "r"(a[1]), "r"(a[2]), "r"(a[3]), "r"(b0), "r"(b1));
}

__device__ __forceinline__ void ldsm4(unsigned* r, unsigned addr) {
    asm volatile("ldmatrix.sync.aligned.m8n8.x4.shared.b16 {%0,%1,%2,%3}, [%4];"
                 : "=r"(r[0]), "=r"(r[1]), "=r"(r[2]), "=r"(r[3]) : "r"(addr));
}

__device__ __forceinline__ void ldsm4t(unsigned* r, unsigned addr) {
    asm volatile("ldmatrix.sync.aligned.m8n8.x4.trans.shared.b16 {%0,%1,%2,%3}, [%4];"
                 : "=r"(r[0]), "=r"(r[1]), "=r"(r[2]), "=r"(r[3]) : "r"(addr));
}

__device__ __forceinline__ void cp_async16(unsigned dst, const void* src) {
    asm volatile("cp.async.cg.shared.global [%0], [%1], 16;\n"
                 :: "r"(dst), "l"(src));
}
__device__ __forceinline__ void cp_commit() {
    asm volatile("cp.async.commit_group;\n");
}
template <int N>
__device__ __forceinline__ void cp_wait() {
    asm volatile("cp.async.wait_group %0;\n" :: "n"(N));
}

// ---------------------------------------------------------------------------
// Kernel 0: per-batch valid length (mask is a prefix mask; length = sum)
// ---------------------------------------------------------------------------
__global__ void len_kernel(const int* __restrict__ mask) {
    int b = blockIdx.x;
    int tid = threadIdx.x;
    const int4* m4 = (const int4*)(mask + b * Tn);
    int sum = 0;
    #pragma unroll
    for (int i = 0; i < 4; i++) {
        int4 v = m4[tid + i * 256];
        sum += v.x + v.y + v.z + v.w;
    }
    __shared__ int red[8];
    #pragma unroll
    for (int off = 16; off > 0; off >>= 1)
        sum += __shfl_down_sync(0xffffffffu, sum, off);
    if ((tid & 31) == 0) red[tid >> 5] = sum;
    __syncthreads();
    if (tid == 0) {
        int s = 0;
        #pragma unroll
        for (int w = 0; w < 8; w++) s += red[w];
        g_len[b] = s;
    }
}

// ---------------------------------------------------------------------------
// Kernel 1: fused QKV projection + RoPE via HMMA (fp32 accum for accuracy).
// ---------------------------------------------------------------------------
__global__ __launch_bounds__(384) void qkv_kernel(
    const float* __restrict__ x,
    const float* __restrict__ Wq,
    const float* __restrict__ Wk,
    const float* __restrict__ Wv,
    const float* __restrict__ fcos,
    const float* __restrict__ fsin)
{
    __shared__ __half Ws[3 * 128 * 64];     // 48KB: [mat][k=128][n=64], swizzled
    int tid = threadIdx.x;

    #pragma unroll
    for (int i = 0; i < 8; i++) {
        int cid = tid + i * 384;
        int mat = cid >> 10;
        int within = cid & 1023;
        int row = within >> 3, c = within & 7;
        const float* src = (mat == 0 ? Wq : (mat == 1 ? Wk : Wv)) + row * 64 + c * 8;
        float4 f0 = *(const float4*)src;
        float4 f1 = *(const float4*)(src + 4);
        union { __half2 h[4]; uint4 u; } pk;
        pk.h[0] = __floats2half2_rn(f0.x, f0.y);
        pk.h[1] = __floats2half2_rn(f0.z, f0.w);
        pk.h[2] = __floats2half2_rn(f1.x, f1.y);
        pk.h[3] = __floats2half2_rn(f1.z, f1.w);
        int dst = mat * 8192 + row * 64 + ((c ^ (row & 7)) * 8);
        *(uint4*)(Ws + dst) = pk.u;
    }
    __syncthreads();

    int w = tid >> 5, lane = tid & 31;
    int g = lane >> 2, tq = lane & 3;
    int mat = w >> 2, rg = w & 3;
    long rowa = (long)blockIdx.x * 64 + rg * 16 + g;

    float acc[8][4];
    #pragma unroll
    for (int n = 0; n < 8; n++) { acc[n][0] = acc[n][1] = acc[n][2] = acc[n][3] = 0.f; }

    unsigned wsb = smem_u32(Ws) + (unsigned)mat * 16384u;
    int grp = lane >> 3, r8 = lane & 7;
    unsigned wrow = (unsigned)(8 * (grp & 1) + r8) * 128u;
    unsigned wsw[4];
    #pragma unroll
    for (int pv = 0; pv < 4; pv++)
        wsw[pv] = (unsigned)(((2 * pv + (grp >> 1)) ^ r8) * 16);

    const float* xa = x + rowa * Cn;
    const float* xb = xa + 8 * Cn;

    #pragma unroll
    for (int ks = 0; ks < 8; ks++) {
        int off = ks * 16 + 2 * tq;
        float2 fa0 = *(const float2*)(xa + off);
        float2 fb0 = *(const float2*)(xb + off);
        float2 fa1 = *(const float2*)(xa + off + 8);
        float2 fb1 = *(const float2*)(xb + off + 8);
        union { __half2 h; unsigned u; } a0, a1, a2, a3;
        a0.h = __floats2half2_rn(fa0.x, fa0.y);
        a1.h = __floats2half2_rn(fb0.x, fb0.y);
        a2.h = __floats2half2_rn(fa1.x, fa1.y);
        a3.h = __floats2half2_rn(fb1.x, fb1.y);
        unsigned a[4] = { a0.u, a1.u, a2.u, a3.u };

        unsigned kbase = wsb + (unsigned)(16 * ks) * 128u + wrow;
        #pragma unroll
        for (int pv = 0; pv < 4; pv++) {
            unsigned wb[4];
            ldsm4t(wb, kbase + wsw[pv]);
            mma16816(acc[2 * pv],     a, wb[0], wb[1]);
            mma16816(acc[2 * pv + 1], a, wb[2], wb[3]);
        }
    }

    int ta = (int)(rowa & (Tn - 1));
    __half* dst = (mat == 0) ? g_Q : (mat == 1 ? g_K : g_V);
    long basea = rowa * HSn;
    long baseb = basea + 8 * HSn;

    if (mat <= 1) {
        float sc = (mat == 0) ? QSCALE : 1.f;
        const float* fca = fcos + (long)ta * 32;
        const float* fsa = fsin + (long)ta * 32;
        #pragma unroll
        for (int n = 0; n < 8; n++) {
            int p = n * 4 + tq;
            float ca = fca[p],       sa = fsa[p];
            float cb = fca[256 + p], sb = fsa[256 + p];   // token ta+8
            float c0 = acc[n][0] * sc, c1 = acc[n][1] * sc;
            float c2 = acc[n][2] * sc, c3 = acc[n][3] * sc;
            __half2 ra = __floats2half2_rn(c0 * ca - c1 * sa, c0 * sa + c1 * ca);
            __half2 rb = __floats2half2_rn(c2 * cb - c3 * sb, c2 * sb + c3 * cb);
            *(__half2*)(dst + basea + n * 8 + 2 * tq) = ra;
            *(__half2*)(dst + baseb + n * 8 + 2 * tq) = rb;
        }
    } else {
        #pragma unroll
        for (int n = 0; n < 8; n++) {
            __half2 ra = __floats2half2_rn(acc[n][0], acc[n][1]);
            __half2 rb = __floats2half2_rn(acc[n][2], acc[n][3]);
            *(__half2*)(dst + basea + n * 8 + 2 * tq) = ra;
            *(__half2*)(dst + baseb + n * 8 + 2 * tq) = rb;
        }
    }
}

// ---------------------------------------------------------------------------
// Kernel 2: flash attention, fp16-accum HMMA, BQ=128 (8 warps), split-K x2,
// double-buffered cp.async pipeline.
// __launch_bounds__(256, 2): force regs <= 128 so 2 CTAs co-reside per SM
// (cross-CTA latency hiding). Heavy-first CTA order (reversed j): the
// longest causal diagonals launch in wave 1 (LPT scheduling).
// ---------------------------------------------------------------------------
__global__ __launch_bounds__(256, 2) void flash_kernel()
{
    __shared__ __half Ks[2][64 * HSn];
    __shared__ __half Vs[2][64 * HSn];

    int b = blockIdx.y;
    // heavy-first: largest j (most key tiles) gets the earliest blockIdx
    int j = (int)(gridDim.x >> 1) - 1 - (int)(blockIdx.x >> 1);
    int half = blockIdx.x & 1;
    int q0 = j * BQ;
    int tid = threadIdx.x, warp = tid >> 5, lane = tid & 31;
    int g = lane >> 2, t = lane & 3;
    int qw = q0 + warp * 16;
    int len = g_len[b];
    int kend = min(q0 + BQ, len);
    int nt = (kend + 63) >> 6;
    int ti0 = half ? (nt >> 1) : 0;
    int ti1 = half ? nt : (nt >> 1);

    unsigned qf[4][4];
    {
        const __half* Qb = g_Q + ((long)b * Tn + qw) * HSn;
        #pragma unroll
        for (int ks = 0; ks < 4; ks++) {
            qf[ks][0] = *(const unsigned*)(Qb + (g    ) * HSn + ks * 16 + 2 * t);
            qf[ks][1] = *(const unsigned*)(Qb + (g + 8) * HSn + ks * 16 + 2 * t);
            qf[ks][2] = *(const unsigned*)(Qb + (g    ) * HSn + ks * 16 + 2 * t + 8);
            qf[ks][3] = *(const unsigned*)(Qb + (g + 8) * HSn + ks * 16 + 2 * t + 8);
        }
    }

    float o[8][4];
    #pragma unroll
    for (int n = 0; n < 8; n++) { o[n][0] = o[n][1] = o[n][2] = o[n][3] = 0.f; }
    float m0 = -1e30f, m1 = -1e30f, l0 = 0.f, l1 = 0.f;

    unsigned ksb = smem_u32(Ks), vsb = smem_u32(Vs);
    int grp = lane >> 3, r8 = lane & 7;
    unsigned kAdr[4], kSw[4], vAdr[4], vSw[4];
    #pragma unroll
    for (int p = 0; p < 4; p++)
        kAdr[p] = ksb + (unsigned)(16 * p + 8 * (grp >> 1) + r8) * 128u;
    #pragma unroll
    for (int ks = 0; ks < 4; ks++)
        kSw[ks] = (unsigned)(((2 * ks + (grp & 1)) ^ r8) * 16);
    #pragma unroll
    for (int kv = 0; kv < 4; kv++)
        vAdr[kv] = vsb + (unsigned)(16 * kv + 8 * (grp & 1) + r8) * 128u;
    #pragma unroll
    for (int pv = 0; pv < 4; pv++)
        vSw[pv] = (unsigned)(((2 * pv + (grp >> 1)) ^ r8) * 16);

    const __half* Kg = g_K + (long)b * Tn * HSn;
    const __half* Vg = g_V + (long)b * Tn * HSn;

    auto load_tile = [&](int bu, int kt) {
        unsigned bo = (unsigned)bu * 8192u;
        #pragma unroll
        for (int i = 0; i < 2; i++) {
            int cid = tid + i * 256;               // 0..511
            int row = cid >> 3, c = cid & 7;
            unsigned dst = (unsigned)(row * HSn + ((c ^ (row & 7)) * 8)) * 2u + bo;
            cp_async16(ksb + dst, Kg + (long)(kt + row) * HSn + c * 8);
            cp_async16(vsb + dst, Vg + (long)(kt + row) * HSn + c * 8);
        }
    };

    const __half HM = __float2half_rn(-60000.f);   // finite mask; exp2 underflows to 0

    int buf = 0;
    if (ti0 < ti1) { load_tile(0, ti0 * 64); cp_commit(); }

    for (int ti = ti0; ti < ti1; ti++) {
        int kt = ti * 64;
        if (ti + 1 < ti1) {
            load_tile(buf ^ 1, (ti + 1) * 64);
            cp_commit();
            cp_wait<1>();
        } else {
            cp_wait<0>();
        }
        __syncthreads();

        unsigned bo = (unsigned)buf * 8192u;

        // S = Q K^T in fp16 accum: sreg[n] = {row g half2, row g+8 half2}
        unsigned sreg[8][2];
        #pragma unroll
        for (int n = 0; n < 8; n++) { sreg[n][0] = 0u; sreg[n][1] = 0u; }
        #pragma unroll
        for (int ks = 0; ks < 4; ks++) {
            #pragma unroll
            for (int p = 0; p < 4; p++) {
                unsigned kb[4];
                ldsm4(kb, kAdr[p] + bo + kSw[ks]);
                mma16816h(sreg[2 * p],     qf[ks], kb[0], kb[1]);
                mma16816h(sreg[2 * p + 1], qf[ks], kb[2], kb[3]);
            }
        }

        // mask (only diagonal / tail tiles)
        bool full = (kt + 63 <= qw) && (kt + 64 <= len);
        if (!full) {
            int rg = qw + g, rg8 = rg + 8;
            #pragma unroll
            for (int n = 0; n < 8; n++) {
                int k0 = kt + n * 8 + 2 * t;
                __half2 v0 = *reinterpret_cast<__half2*>(&sreg[n][0]);
                __half2 v1 = *reinterpret_cast<__half2*>(&sreg[n][1]);
                if (!(k0     <= rg  && k0     < len)) v0.x = HM;
                if (!(k0 + 1 <= rg  && k0 + 1 < len)) v0.y = HM;
                if (!(k0     <= rg8 && k0     < len)) v1.x = HM;
                if (!(k0 + 1 <= rg8 && k0 + 1 < len)) v1.y = HM;
                sreg[n][0] = *reinterpret_cast<unsigned*>(&v0);
                sreg[n][1] = *reinterpret_cast<unsigned*>(&v1);
            }
        }

        // row max via half2 trees (rows g and g+8), finalize fp32
        {
            __half2 h0 = *reinterpret_cast<__half2*>(&sreg[0][0]);
            __half2 h1 = *reinterpret_cast<__half2*>(&sreg[0][1]);
            #pragma unroll
            for (int n = 1; n < 8; n++) {
                h0 = __hmax2(h0, *reinterpret_cast<__half2*>(&sreg[n][0]));
                h1 = __hmax2(h1, *reinterpret_cast<__half2*>(&sreg[n][1]));
            }
            float2 f0 = __half22float2(h0);
            float2 f1 = __half22float2(h1);
            float mr0 = fmaxf(f0.x, f0.y);
            float mr1 = fmaxf(f1.x, f1.y);
            mr0 = fmaxf(mr0, __shfl_xor_sync(0xffffffffu, mr0, 1));
            mr0 = fmaxf(mr0, __shfl_xor_sync(0xffffffffu, mr0, 2));
            mr1 = fmaxf(mr1, __shfl_xor_sync(0xffffffffu, mr1, 1));
            mr1 = fmaxf(mr1, __shfl_xor_sync(0xffffffffu, mr1, 2));

            float mn0 = fmaxf(m0, mr0), mn1 = fmaxf(m1, mr1);
            float a0 = exp2_approx(m0 - mn0), a1 = exp2_approx(m1 - mn1);
            m0 = mn0; m1 = mn1;
            l0 *= a0;  l1 *= a1;

            // p = exp2(s - mn) in-place (f16x2) -> directly the PV A-operand
            __half2 mh0 = __float2half2_rn(mn0);
            __half2 mh1 = __float2half2_rn(mn1);
            float ls0 = 0.f, ls1 = 0.f;
            #pragma unroll
            for (int n = 0; n < 8; n++) {
                __half2 d0 = __hsub2(*reinterpret_cast<__half2*>(&sreg[n][0]), mh0);
                __half2 d1 = __hsub2(*reinterpret_cast<__half2*>(&sreg[n][1]), mh1);
                sreg[n][0] = exp2_h2(*reinterpret_cast<unsigned*>(&d0));
                sreg[n][1] = exp2_h2(*reinterpret_cast<unsigned*>(&d1));
                float2 p0 = __half22float2(*reinterpret_cast<__half2*>(&sreg[n][0]));
                float2 p1 = __half22float2(*reinterpret_cast<__half2*>(&sreg[n][1]));
                ls0 += p0.x + p0.y;
                ls1 += p1.x + p1.y;
            }
            l0 += ls0; l1 += ls1;

            // O += P V  (fp16 accum per tile, fp32 carry across tiles)
            unsigned dreg[8][2];
            #pragma unroll
            for (int n = 0; n < 8; n++) { dreg[n][0] = 0u; dreg[n][1] = 0u; }
            #pragma unroll
            for (int kv = 0; kv < 4; kv++) {
                unsigned pa[4] = { sreg[2 * kv][0], sreg[2 * kv][1],
                                   sreg[2 * kv + 1][0], sreg[2 * kv + 1][1] };
                #pragma unroll
                for (int pv = 0; pv < 4; pv++) {
                    unsigned vb[4];
                    ldsm4t(vb, vAdr[kv] + bo + vSw[pv]);
                    mma16816h(dreg[2 * pv],     pa, vb[0], vb[1]);
                    mma16816h(dreg[2 * pv + 1], pa, vb[2], vb[3]);
                }
            }
            #pragma unroll
            for (int n = 0; n < 8; n++) {
                float2 d0 = __half22float2(*reinterpret_cast<__half2*>(&dreg[n][0]));
                float2 d1 = __half22float2(*reinterpret_cast<__half2*>(&dreg[n][1]));
                o[n][0] = o[n][0] * a0 + d0.x;
                o[n][1] = o[n][1] * a0 + d0.y;
                o[n][2] = o[n][2] * a1 + d1.x;
                o[n][3] = o[n][3] * a1 + d1.y;
            }
        }
        __syncthreads();   // all warps done with buf before it is overwritten
        buf ^= 1;
    }

    l0 += __shfl_xor_sync(0xffffffffu, l0, 1);
    l0 += __shfl_xor_sync(0xffffffffu, l0, 2);
    l1 += __shfl_xor_sync(0xffffffffu, l1, 1);
    l1 += __shfl_xor_sync(0xffffffffu, l1, 2);

    long rbase = (long)b * Tn + qw;
    float* ob = g_po + ((long)half * Bn * Tn + rbase) * HSn;
    #pragma unroll
    for (int n = 0; n < 8; n++) {
        float2 v0 = { o[n][0], o[n][1] };
        float2 v1 = { o[n][2], o[n][3] };
        *(float2*)(ob + (g    ) * HSn + n * 8 + 2 * t) = v0;
        *(float2*)(ob + (g + 8) * HSn + n * 8 + 2 * t) = v1;
    }
    if (t == 0) {
        long pr = (long)half * Bn * Tn + rbase;
        g_pm[pr + g]     = m0;  g_pl[pr + g]     = l0;
        g_pm[pr + g + 8] = m1;  g_pl[pr + g + 8] = l1;
    }
}

// ---------------------------------------------------------------------------
// Kernel 3: merge the two split-K partials and normalize.
// ---------------------------------------------------------------------------
__global__ __launch_bounds__(256) void merge_kernel(float* __restrict__ out)
{
    int tid = threadIdx.x;
    long r = (long)blockIdx.x * 32 + (tid >> 3);
    int d0 = (tid & 7) * 8;

    float m0 = g_pm[r], l0 = g_pl[r];
    float m1 = g_pm[(long)Bn * Tn + r], l1 = g_pl[(long)Bn * Tn + r];
    float ms = fmaxf(m0, m1);
    float s0 = exp2_approx(m0 - ms);
    float s1 = exp2_approx(m1 - ms);
    float inv = 1.f / (l0 * s0 + l1 * s1);
    s0 *= inv; s1 *= inv;

    long base = r * HSn + d0;
    const float4* p0 = (const float4*)(g_po + base);
    const float4* p1 = (const float4*)(g_po + (long)Bn * Tn * HSn + base);
    float4* po = (float4*)(out + base);
    #pragma unroll
    for (int i = 0; i < 2; i++) {
        float4 a = p0[i], c = p1[i];
        float4 rr;
        rr.x = a.x * s0 + c.x * s1;
        rr.y = a.y * s0 + c.y * s1;
        rr.z = a.z * s0 + c.z * s1;
        rr.w = a.w * s0 + c.w * s1;
        po[i] = rr;
    }
}

// ---------------------------------------------------------------------------
extern "C" void kernel_launch(void* const* d_in, const int* in_sizes, int n_in,
                              void* d_out, int out_size) {
    const float* x    = (const float*)d_in[0];
    const float* Wq   = (const float*)d_in[1];
    const float* Wk   = (const float*)d_in[2];
    const float* Wv   = (const float*)d_in[3];
    const float* fcos = (const float*)d_in[4];
    const float* fsin = (const float*)d_in[5];
    const int*   mask = (const int*)d_in[6];
    float* out = (float*)d_out;

    len_kernel<<<Bn, 256>>>(mask);
    qkv_kernel<<<Bn * Tn / 64, 384>>>(x, Wq, Wk, Wv, fcos, fsin);
    dim3 grid(2 * Tn / BQ, Bn);
    flash_kernel<<<grid, 256>>>();
    merge_kernel<<<Bn * Tn / 32, 256>>>(out);
}

// round 13
// speedup vs baseline: 11.5771x; 1.0233x over previous
#include <cuda_runtime.h>
#include <cuda_fp16.h>
#include <cstdint>
#include <stdint.h>

#define Bn 8
#define Tn 4096
#define Cn 128
#define HSn 64
#define BQ 128

// scale = 1/sqrt(C) folded with log2(e) so we can use ex2.approx
#define QSCALE (0.08838834764831845f * 1.4426950408889634f)

// Scratch (device globals — no allocation allowed in kernel_launch)
__device__ __align__(16) __half g_Q[Bn * Tn * HSn];
__device__ __align__(16) __half g_K[Bn * Tn * HSn];
__device__ __align__(16) __half g_V[Bn * Tn * HSn];
__device__ __align__(16) __half g_po[2 * Bn * Tn * HSn];  // NORMALIZED O partials (fp16)
__device__ float g_pm[2 * Bn * Tn];
__device__ float g_pl[2 * Bn * Tn];
__device__ int g_len[Bn];

__device__ __forceinline__ float exp2_approx(float x) {
    float y;
    asm("ex2.approx.ftz.f32 %0, %1;" : "=f"(y) : "f"(x));
    return y;
}

__device__ __forceinline__ unsigned exp2_h2(unsigned x) {
    unsigned y;
    asm("ex2.approx.f16x2 %0, %1;" : "=r"(y) : "r"(x));
    return y;
}

__device__ __forceinline__ unsigned smem_u32(const void* p) {
    return (unsigned)__cvta_generic_to_shared(p);
}

// fp32-accum HMMA (qkv kernel)
__device__ __forceinline__ void mma16816(float* c, const unsigned* a,
                                         unsigned b0, unsigned b1) {
    asm volatile(
        "mma.sync.aligned.m16n8k16.row.col.f32.f16.f16.f32 "
        "{%0,%1,%2,%3}, {%4,%5,%6,%7}, {%8,%9}, {%0,%1,%2,%3};\n"
        : "+f"(c[0]), "+f"(c[1]), "+f"(c[2]), "+f"(c[3])
        : "r"(a[0]), "r"(a[1]), "r"(a[2]), "r"(a[3]), "r"(b0), "r"(b1));
}

// fp16-accum HMMA (flash kernel) — C fragment == A fragment layout
__device__ __forceinline__ void mma16816h(unsigned* c, const unsigned* a,
                                          unsigned b0, unsigned b1) {
    asm volatile(
        "mma.sync.aligned.m16n8k16.row.col.f16.f16.f16.f16 "
        "{%0,%1}, {%2,%3,%4,%5}, {%6,%7}, {%0,%1};\n"
        : "+r"(c[0]), "+r"(c[1])
        : "r"(a[0]), "r"(a[1]), "r"(a[2]), "r"(a[3]), "r"(b0), "r"(b1));
}

__device__ __forceinline__ void ldsm4(unsigned* r, unsigned addr) {
    asm volatile("ldmatrix.sync.aligned.m8n8.x4.shared.b16 {%0,%1,%2,%3}, [%4];"
                 : "=r"(r[0]), "=r"(r[1]), "=r"(r[2]), "=r"(r[3]) : "r"(addr));
}

__device__ __forceinline__ void ldsm4t(unsigned* r, unsigned addr) {
    asm volatile("ldmatrix.sync.aligned.m8n8.x4.trans.shared.b16 {%0,%1,%2,%3}, [%4];"
                 : "=r"(r[0]), "=r"(r[1]), "=r"(r[2]), "=r"(r[3]) : "r"(addr));
}

__device__ __forceinline__ void cp_async16(unsigned dst, const void* src) {
    asm volatile("cp.async.cg.shared.global [%0], [%1], 16;\n"
                 :: "r"(dst), "l"(src));
}
__device__ __forceinline__ void cp_commit() {
    asm volatile("cp.async.commit_group;\n");
}
template <int N>
__device__ __forceinline__ void cp_wait() {
    asm volatile("cp.async.wait_group %0;\n" :: "n"(N));
}

// ---------------------------------------------------------------------------
// Kernel 0: per-batch valid length (mask is a prefix mask; length = sum)
// ---------------------------------------------------------------------------
__global__ void len_kernel(const int* __restrict__ mask) {
    int b = blockIdx.x;
    int tid = threadIdx.x;
    const int4* m4 = (const int4*)(mask + b * Tn);
    int sum = 0;
    #pragma unroll
    for (int i = 0; i < 4; i++) {
        int4 v = m4[tid + i * 256];
        sum += v.x + v.y + v.z + v.w;
    }
    __shared__ int red[8];
    #pragma unroll
    for (int off = 16; off > 0; off >>= 1)
        sum += __shfl_down_sync(0xffffffffu, sum, off);
    if ((tid & 31) == 0) red[tid >> 5] = sum;
    __syncthreads();
    if (tid == 0) {
        int s = 0;
        #pragma unroll
        for (int w = 0; w < 8; w++) s += red[w];
        g_len[b] = s;
    }
}

// ---------------------------------------------------------------------------
// Kernel 1: fused QKV projection + RoPE via HMMA (fp32 accum for accuracy).
// ---------------------------------------------------------------------------
__global__ __launch_bounds__(384) void qkv_kernel(
    const float* __restrict__ x,
    const float* __restrict__ Wq,
    const float* __restrict__ Wk,
    const float* __restrict__ Wv,
    const float* __restrict__ fcos,
    const float* __restrict__ fsin)
{
    __shared__ __half Ws[3 * 128 * 64];     // 48KB: [mat][k=128][n=64], swizzled
    int tid = threadIdx.x;

    #pragma unroll
    for (int i = 0; i < 8; i++) {
        int cid = tid + i * 384;
        int mat = cid >> 10;
        int within = cid & 1023;
        int row = within >> 3, c = within & 7;
        const float* src = (mat == 0 ? Wq : (mat == 1 ? Wk : Wv)) + row * 64 + c * 8;
        float4 f0 = *(const float4*)src;
        float4 f1 = *(const float4*)(src + 4);
        union { __half2 h[4]; uint4 u; } pk;
        pk.h[0] = __floats2half2_rn(f0.x, f0.y);
        pk.h[1] = __floats2half2_rn(f0.z, f0.w);
        pk.h[2] = __floats2half2_rn(f1.x, f1.y);
        pk.h[3] = __floats2half2_rn(f1.z, f1.w);
        int dst = mat * 8192 + row * 64 + ((c ^ (row & 7)) * 8);
        *(uint4*)(Ws + dst) = pk.u;
    }
    __syncthreads();

    int w = tid >> 5, lane = tid & 31;
    int g = lane >> 2, tq = lane & 3;
    int mat = w >> 2, rg = w & 3;
    long rowa = (long)blockIdx.x * 64 + rg * 16 + g;

    float acc[8][4];
    #pragma unroll
    for (int n = 0; n < 8; n++) { acc[n][0] = acc[n][1] = acc[n][2] = acc[n][3] = 0.f; }

    unsigned wsb = smem_u32(Ws) + (unsigned)mat * 16384u;
    int grp = lane >> 3, r8 = lane & 7;
    unsigned wrow = (unsigned)(8 * (grp & 1) + r8) * 128u;
    unsigned wsw[4];
    #pragma unroll
    for (int pv = 0; pv < 4; pv++)
        wsw[pv] = (unsigned)(((2 * pv + (grp >> 1)) ^ r8) * 16);

    const float* xa = x + rowa * Cn;
    const float* xb = xa + 8 * Cn;

    #pragma unroll
    for (int ks = 0; ks < 8; ks++) {
        int off = ks * 16 + 2 * tq;
        float2 fa0 = *(const float2*)(xa + off);
        float2 fb0 = *(const float2*)(xb + off);
        float2 fa1 = *(const float2*)(xa + off + 8);
        float2 fb1 = *(const float2*)(xb + off + 8);
        union { __half2 h; unsigned u; } a0, a1, a2, a3;
        a0.h = __floats2half2_rn(fa0.x, fa0.y);
        a1.h = __floats2half2_rn(fb0.x, fb0.y);
        a2.h = __floats2half2_rn(fa1.x, fa1.y);
        a3.h = __floats2half2_rn(fb1.x, fb1.y);
        unsigned a[4] = { a0.u, a1.u, a2.u, a3.u };

        unsigned kbase = wsb + (unsigned)(16 * ks) * 128u + wrow;
        #pragma unroll
        for (int pv = 0; pv < 4; pv++) {
            unsigned wb[4];
            ldsm4t(wb, kbase + wsw[pv]);
            mma16816(acc[2 * pv],     a, wb[0], wb[1]);
            mma16816(acc[2 * pv + 1], a, wb[2], wb[3]);
        }
    }

    int ta = (int)(rowa & (Tn - 1));
    __half* dst = (mat == 0) ? g_Q : (mat == 1 ? g_K : g_V);
    long basea = rowa * HSn;
    long baseb = basea + 8 * HSn;

    if (mat <= 1) {
        float sc = (mat == 0) ? QSCALE : 1.f;
        const float* fca = fcos + (long)ta * 32;
        const float* fsa = fsin + (long)ta * 32;
        #pragma unroll
        for (int n = 0; n < 8; n++) {
            int p = n * 4 + tq;
            float ca = fca[p],       sa = fsa[p];
            float cb = fca[256 + p], sb = fsa[256 + p];   // token ta+8
            float c0 = acc[n][0] * sc, c1 = acc[n][1] * sc;
            float c2 = acc[n][2] * sc, c3 = acc[n][3] * sc;
            __half2 ra = __floats2half2_rn(c0 * ca - c1 * sa, c0 * sa + c1 * ca);
            __half2 rb = __floats2half2_rn(c2 * cb - c3 * sb, c2 * sb + c3 * cb);
            *(__half2*)(dst + basea + n * 8 + 2 * tq) = ra;
            *(__half2*)(dst + baseb + n * 8 + 2 * tq) = rb;
        }
    } else {
        #pragma unroll
        for (int n = 0; n < 8; n++) {
            __half2 ra = __floats2half2_rn(acc[n][0], acc[n][1]);
            __half2 rb = __floats2half2_rn(acc[n][2], acc[n][3]);
            *(__half2*)(dst + basea + n * 8 + 2 * tq) = ra;
            *(__half2*)(dst + baseb + n * 8 + 2 * tq) = rb;
        }
    }
}

// ---------------------------------------------------------------------------
// Kernel 2: flash attention, fp16-accum HMMA, BQ=128 (8 warps), split-K x2.
// 3-stage cp.async ring with ONE __syncthreads per tile: warps may skew by
// a full iteration, overlapping one warp's softmax with others' MMA issue.
// Stores NORMALIZED fp16 partials (o/l) + fp32 (m, l).
// ---------------------------------------------------------------------------
__global__ __launch_bounds__(256, 2) void flash_kernel()
{
    __shared__ __half Ks[3][64 * HSn];
    __shared__ __half Vs[3][64 * HSn];

    int b = blockIdx.y;
    // heavy-first: largest j (most key tiles) gets the earliest blockIdx
    int j = (int)(gridDim.x >> 1) - 1 - (int)(blockIdx.x >> 1);
    int half = blockIdx.x & 1;
    int q0 = j * BQ;
    int tid = threadIdx.x, warp = tid >> 5, lane = tid & 31;
    int g = lane >> 2, t = lane & 3;
    int qw = q0 + warp * 16;
    int len = g_len[b];
    int kend = min(q0 + BQ, len);
    int nt = (kend + 63) >> 6;
    int ti0 = half ? (nt >> 1) : 0;
    int ti1 = half ? nt : (nt >> 1);

    unsigned qf[4][4];
    {
        const __half* Qb = g_Q + ((long)b * Tn + qw) * HSn;
        #pragma unroll
        for (int ks = 0; ks < 4; ks++) {
            qf[ks][0] = *(const unsigned*)(Qb + (g    ) * HSn + ks * 16 + 2 * t);
            qf[ks][1] = *(const unsigned*)(Qb + (g + 8) * HSn + ks * 16 + 2 * t);
            qf[ks][2] = *(const unsigned*)(Qb + (g    ) * HSn + ks * 16 + 2 * t + 8);
            qf[ks][3] = *(const unsigned*)(Qb + (g + 8) * HSn + ks * 16 + 2 * t + 8);
        }
    }

    float o[8][4];
    #pragma unroll
    for (int n = 0; n < 8; n++) { o[n][0] = o[n][1] = o[n][2] = o[n][3] = 0.f; }
    float m0 = -1e30f, m1 = -1e30f, l0 = 0.f, l1 = 0.f;

    unsigned ksb = smem_u32(Ks), vsb = smem_u32(Vs);
    int grp = lane >> 3, r8 = lane & 7;
    unsigned kAdr[4], kSw[4], vAdr[4], vSw[4];
    #pragma unroll
    for (int p = 0; p < 4; p++)
        kAdr[p] = ksb + (unsigned)(16 * p + 8 * (grp >> 1) + r8) * 128u;
    #pragma unroll
    for (int ks = 0; ks < 4; ks++)
        kSw[ks] = (unsigned)(((2 * ks + (grp & 1)) ^ r8) * 16);
    #pragma unroll
    for (int kv = 0; kv < 4; kv++)
        vAdr[kv] = vsb + (unsigned)(16 * kv + 8 * (grp & 1) + r8) * 128u;
    #pragma unroll
    for (int pv = 0; pv < 4; pv++)
        vSw[pv] = (unsigned)(((2 * pv + (grp >> 1)) ^ r8) * 16);

    const __half* Kg = g_K + (long)b * Tn * HSn;
    const __half* Vg = g_V + (long)b * Tn * HSn;

    auto load_tile = [&](int st, int kt) {
        unsigned bo = (unsigned)st * 8192u;
        #pragma unroll
        for (int i = 0; i < 2; i++) {
            int cid = tid + i * 256;               // 0..511
            int row = cid >> 3, c = cid & 7;
            unsigned dst = (unsigned)(row * HSn + ((c ^ (row & 7)) * 8)) * 2u + bo;
            cp_async16(ksb + dst, Kg + (long)(kt + row) * HSn + c * 8);
            cp_async16(vsb + dst, Vg + (long)(kt + row) * HSn + c * 8);
        }
    };

    const __half HM = __float2half_rn(-60000.f);   // finite mask; exp2 underflows to 0

    int buf = 0;
    if (ti0 < ti1) { load_tile(0, ti0 * 64); cp_commit(); }

    for (int ti = ti0; ti < ti1; ti++) {
        int kt = ti * 64;
        int nstage = (buf == 2) ? 0 : buf + 1;
        if (ti + 1 < ti1) {
            load_tile(nstage, (ti + 1) * 64);
            cp_commit();
            cp_wait<1>();
        } else {
            cp_wait<0>();
        }
        __syncthreads();          // single barrier per tile (3-stage ring)

        unsigned bo = (unsigned)buf * 8192u;

        // S = Q K^T in fp16 accum: sreg[n] = {row g half2, row g+8 half2}
        unsigned sreg[8][2];
        #pragma unroll
        for (int n = 0; n < 8; n++) { sreg[n][0] = 0u; sreg[n][1] = 0u; }
        #pragma unroll
        for (int ks = 0; ks < 4; ks++) {
            #pragma unroll
            for (int p = 0; p < 4; p++) {
                unsigned kb[4];
                ldsm4(kb, kAdr[p] + bo + kSw[ks]);
                mma16816h(sreg[2 * p],     qf[ks], kb[0], kb[1]);
                mma16816h(sreg[2 * p + 1], qf[ks], kb[2], kb[3]);
            }
        }

        // mask (only diagonal / tail tiles)
        bool full = (kt + 63 <= qw) && (kt + 64 <= len);
        if (!full) {
            int rg = qw + g, rg8 = rg + 8;
            #pragma unroll
            for (int n = 0; n < 8; n++) {
                int k0 = kt + n * 8 + 2 * t;
                __half2 v0 = *reinterpret_cast<__half2*>(&sreg[n][0]);
                __half2 v1 = *reinterpret_cast<__half2*>(&sreg[n][1]);
                if (!(k0     <= rg  && k0     < len)) v0.x = HM;
                if (!(k0 + 1 <= rg  && k0 + 1 < len)) v0.y = HM;
                if (!(k0     <= rg8 && k0     < len)) v1.x = HM;
                if (!(k0 + 1 <= rg8 && k0 + 1 < len)) v1.y = HM;
                sreg[n][0] = *reinterpret_cast<unsigned*>(&v0);
                sreg[n][1] = *reinterpret_cast<unsigned*>(&v1);
            }
        }

        // row max via half2 trees (rows g and g+8), finalize fp32
        {
            __half2 h0 = *reinterpret_cast<__half2*>(&sreg[0][0]);
            __half2 h1 = *reinterpret_cast<__half2*>(&sreg[0][1]);
            #pragma unroll
            for (int n = 1; n < 8; n++) {
                h0 = __hmax2(h0, *reinterpret_cast<__half2*>(&sreg[n][0]));
                h1 = __hmax2(h1, *reinterpret_cast<__half2*>(&sreg[n][1]));
            }
            float2 f0 = __half22float2(h0);
            float2 f1 = __half22float2(h1);
            float mr0 = fmaxf(f0.x, f0.y);
            float mr1 = fmaxf(f1.x, f1.y);
            mr0 = fmaxf(mr0, __shfl_xor_sync(0xffffffffu, mr0, 1));
            mr0 = fmaxf(mr0, __shfl_xor_sync(0xffffffffu, mr0, 2));
            mr1 = fmaxf(mr1, __shfl_xor_sync(0xffffffffu, mr1, 1));
            mr1 = fmaxf(mr1, __shfl_xor_sync(0xffffffffu, mr1, 2));

            float mn0 = fmaxf(m0, mr0), mn1 = fmaxf(m1, mr1);
            float a0 = exp2_approx(m0 - mn0), a1 = exp2_approx(m1 - mn1);
            m0 = mn0; m1 = mn1;
            l0 *= a0;  l1 *= a1;

            // p = exp2(s - mn) in-place (f16x2) -> directly the PV A-operand
            __half2 mh0 = __float2half2_rn(mn0);
            __half2 mh1 = __float2half2_rn(mn1);
            float ls0 = 0.f, ls1 = 0.f;
            #pragma unroll
            for (int n = 0; n < 8; n++) {
                __half2 d0 = __hsub2(*reinterpret_cast<__half2*>(&sreg[n][0]), mh0);
                __half2 d1 = __hsub2(*reinterpret_cast<__half2*>(&sreg[n][1]), mh1);
                sreg[n][0] = exp2_h2(*reinterpret_cast<unsigned*>(&d0));
                sreg[n][1] = exp2_h2(*reinterpret_cast<unsigned*>(&d1));
                float2 p0 = __half22float2(*reinterpret_cast<__half2*>(&sreg[n][0]));
                float2 p1 = __half22float2(*reinterpret_cast<__half2*>(&sreg[n][1]));
                ls0 += p0.x + p0.y;
                ls1 += p1.x + p1.y;
            }
            l0 += ls0; l1 += ls1;

            // O += P V  (fp16 accum per tile, fp32 carry across tiles)
            unsigned dreg[8][2];
            #pragma unroll
            for (int n = 0; n < 8; n++) { dreg[n][0] = 0u; dreg[n][1] = 0u; }
            #pragma unroll
            for (int kv = 0; kv < 4; kv++) {
                unsigned pa[4] = { sreg[2 * kv][0], sreg[2 * kv][1],
                                   sreg[2 * kv + 1][0], sreg[2 * kv + 1][1] };
                #pragma unroll
                for (int pv = 0; pv < 4; pv++) {
                    unsigned vb[4];
                    ldsm4t(vb, vAdr[kv] + bo + vSw[pv]);
                    mma16816h(dreg[2 * pv],     pa, vb[0], vb[1]);
                    mma16816h(dreg[2 * pv + 1], pa, vb[2], vb[3]);
                }
            }
            #pragma unroll
            for (int n = 0; n < 8; n++) {
                float2 d0 = __half22float2(*reinterpret_cast<__half2*>(&dreg[n][0]));
                float2 d1 = __half22float2(*reinterpret_cast<__half2*>(&dreg[n][1]));
                o[n][0] = o[n][0] * a0 + d0.x;
                o[n][1] = o[n][1] * a0 + d0.y;
                o[n][2] = o[n][2] * a1 + d1.x;
                o[n][3] = o[n][3] * a1 + d1.y;
            }
        }
        buf = nstage;
    }

    l0 += __shfl_xor_sync(0xffffffffu, l0, 1);
    l0 += __shfl_xor_sync(0xffffffffu, l0, 2);
    l1 += __shfl_xor_sync(0xffffffffu, l1, 1);
    l1 += __shfl_xor_sync(0xffffffffu, l1, 2);

    // normalized fp16 partials (guard: empty range -> l == 0 -> store zeros)
    float inv0 = (l0 > 0.f) ? (1.f / l0) : 0.f;
    float inv1 = (l1 > 0.f) ? (1.f / l1) : 0.f;

    long rbase = (long)b * Tn + qw;
    __half* ob = g_po + ((long)half * Bn * Tn + rbase) * HSn;
    #pragma unroll
    for (int n = 0; n < 8; n++) {
        __half2 v0 = __floats2half2_rn(o[n][0] * inv0, o[n][1] * inv0);
        __half2 v1 = __floats2half2_rn(o[n][2] * inv1, o[n][3] * inv1);
        *(__half2*)(ob + (g    ) * HSn + n * 8 + 2 * t) = v0;
        *(__half2*)(ob + (g + 8) * HSn + n * 8 + 2 * t) = v1;
    }
    if (t == 0) {
        long pr = (long)half * Bn * Tn + rbase;
        g_pm[pr + g]     = m0;  g_pl[pr + g]     = l0;
        g_pm[pr + g + 8] = m1;  g_pl[pr + g + 8] = l1;
    }
}

// ---------------------------------------------------------------------------
// Kernel 3: merge the two split-K partials (normalized fp16) and finalize.
// out = sum_i w_i * o_i_norm, with w_i = l_i * 2^(m_i - ms) / D.
// ---------------------------------------------------------------------------
__global__ __launch_bounds__(256) void merge_kernel(float* __restrict__ out)
{
    int tid = threadIdx.x;
    long r = (long)blockIdx.x * 32 + (tid >> 3);
    int d0 = (tid & 7) * 8;

    float m0 = g_pm[r], l0 = g_pl[r];
    float m1 = g_pm[(long)Bn * Tn + r], l1 = g_pl[(long)Bn * Tn + r];
    float ms = fmaxf(m0, m1);
    float w0 = exp2_approx(m0 - ms) * l0;
    float w1 = exp2_approx(m1 - ms) * l1;
    float inv = 1.f / (w0 + w1);
    w0 *= inv; w1 *= inv;

    long base = r * HSn + d0;
    union { uint4 u; __half2 h[4]; } a, c;
    a.u = *(const uint4*)(g_po + base);
    c.u = *(const uint4*)(g_po + (long)Bn * Tn * HSn + base);

    float4 r0, r1;
    {
        float2 a0 = __half22float2(a.h[0]), c0 = __half22float2(c.h[0]);
        float2 a1 = __half22float2(a.h[1]), c1 = __half22float2(c.h[1]);
        r0.x = a0.x * w0 + c0.x * w1;  r0.y = a0.y * w0 + c0.y * w1;
        r0.z = a1.x * w0 + c1.x * w1;  r0.w = a1.y * w0 + c1.y * w1;
        float2 a2 = __half22float2(a.h[2]), c2 = __half22float2(c.h[2]);
        float2 a3 = __half22float2(a.h[3]), c3 = __half22float2(c.h[3]);
        r1.x = a2.x * w0 + c2.x * w1;  r1.y = a2.y * w0 + c2.y * w1;
        r1.z = a3.x * w0 + c3.x * w1;  r1.w = a3.y * w0 + c3.y * w1;
    }
    float4* po = (float4*)(out + base);
    po[0] = r0;
    po[1] = r1;
}

// ---------------------------------------------------------------------------
extern "C" void kernel_launch(void* const* d_in, const int* in_sizes, int n_in,
                              void* d_out, int out_size) {
    const float* x    = (const float*)d_in[0];
    const float* Wq   = (const float*)d_in[1];
    const float* Wk   = (const float*)d_in[2];
    const float* Wv   = (const float*)d_in[3];
    const float* fcos = (const float*)d_in[4];
    const float* fsin = (const float*)d_in[5];
    const int*   mask = (const int*)d_in[6];
    float* out = (float*)d_out;

    len_kernel<<<Bn, 256>>>(mask);
    qkv_kernel<<<Bn * Tn / 64, 384>>>(x, Wq, Wk, Wv, fcos, fsin);
    dim3 grid(2 * Tn / BQ, Bn);
    flash_kernel<<<grid, 256>>>();
    merge_kernel<<<Bn * Tn / 32, 256>>>(out);
}